// round 1
// baseline (speedup 1.0000x reference)
#include <cuda_runtime.h>
#include <math.h>

#define H 128
#define LAYERS 4
#define NMAX 50176
#define EPS 1e-8f

// ---------------- static device scratch (allocation-free rule) ----------------
__device__ float g_h[NMAX * H];
__device__ float g_A[NMAX * H];     // (h @ msgW1[0:128])   -> indexed by dst
__device__ float g_B[NMAX * H];     // (h @ msgW1[128:256]) -> indexed by src
__device__ float g_C1[NMAX * H];    // coord hidden
__device__ float g_agg[NMAX * H];   // message scatter target
__device__ float g_T[NMAX * H];     // generic temp
__device__ float g_pos[NMAX * 3];
__device__ float g_dpos[NMAX * 3];
__device__ float g_wnode[NMAX];

__device__ __forceinline__ float silu_f(float x) {
    return x / (1.0f + __expf(-x));
}

// ---------------- generic node-side GEMM: Y = epi( [X1|X2] @ W + bias ) -------
// Tile 64 rows x 128 cols, 128 threads, 8x8 per thread. W row-major [Ktot,128].
__global__ __launch_bounds__(128) void node_gemm(
    const float* __restrict__ X1, int K1,
    const float* __restrict__ X2, int K2,
    const float* __restrict__ W,
    const float* __restrict__ bias,   // may be null
    const float* __restrict__ res,    // may be null (residual add AFTER act)
    int act,                          // 1 = silu
    float* __restrict__ Y, int n)
{
    __shared__ float Xs[16 * 68];
    __shared__ float Ws[16 * 132];
    const int tid = threadIdx.x;
    const int row0 = blockIdx.x * 64;
    const int tm = tid & 7;        // 8 row groups
    const int tc = tid >> 3;       // 16 col groups

    float acc[8][8];
#pragma unroll
    for (int i = 0; i < 8; i++)
#pragma unroll
        for (int j = 0; j < 8; j++) acc[i][j] = 0.0f;

    const int Ktot = K1 + K2;
    for (int kc = 0; kc < Ktot; kc += 16) {
        const float* src; int stride, col;
        if (kc < K1) { src = X1; stride = K1; col = kc; }
        else         { src = X2; stride = K2; col = kc - K1; }

        // X tile 64x16, store transposed Xs[k][m]
#pragma unroll
        for (int q = tid; q < 256; q += 128) {
            int m = q >> 2, kq = q & 3;
            int row = row0 + m;
            float4 v = make_float4(0.f, 0.f, 0.f, 0.f);
            if (row < n) v = *(const float4*)(src + (size_t)row * stride + col + kq * 4);
            Xs[(kq * 4 + 0) * 68 + m] = v.x;
            Xs[(kq * 4 + 1) * 68 + m] = v.y;
            Xs[(kq * 4 + 2) * 68 + m] = v.z;
            Xs[(kq * 4 + 3) * 68 + m] = v.w;
        }
        // W tile 16x128
#pragma unroll
        for (int q = tid; q < 512; q += 128) {
            int k = q >> 5, c4 = q & 31;
            *(float4*)(Ws + k * 132 + c4 * 4) =
                *(const float4*)(W + (size_t)(kc + k) * H + c4 * 4);
        }
        __syncthreads();

#pragma unroll
        for (int k = 0; k < 16; ++k) {
            float4 a0 = *(const float4*)(Xs + k * 68 + tm * 8);
            float4 a1 = *(const float4*)(Xs + k * 68 + tm * 8 + 4);
            float4 b0 = *(const float4*)(Ws + k * 132 + tc * 8);
            float4 b1 = *(const float4*)(Ws + k * 132 + tc * 8 + 4);
            float av[8] = {a0.x, a0.y, a0.z, a0.w, a1.x, a1.y, a1.z, a1.w};
            float bv[8] = {b0.x, b0.y, b0.z, b0.w, b1.x, b1.y, b1.z, b1.w};
#pragma unroll
            for (int i = 0; i < 8; i++)
#pragma unroll
                for (int j = 0; j < 8; j++)
                    acc[i][j] = fmaf(av[i], bv[j], acc[i][j]);
        }
        __syncthreads();
    }

    float bb[8];
#pragma unroll
    for (int j = 0; j < 8; j++) bb[j] = bias ? bias[tc * 8 + j] : 0.0f;

#pragma unroll
    for (int i = 0; i < 8; i++) {
        int row = row0 + tm * 8 + i;
        if (row >= n) continue;
        float out[8];
#pragma unroll
        for (int j = 0; j < 8; j++) {
            float v = acc[i][j] + bb[j];
            if (act) v = silu_f(v);
            out[j] = v;
        }
        if (res) {
            float4 r0 = *(const float4*)(res + (size_t)row * H + tc * 8);
            float4 r1 = *(const float4*)(res + (size_t)row * H + tc * 8 + 4);
            out[0] += r0.x; out[1] += r0.y; out[2] += r0.z; out[3] += r0.w;
            out[4] += r1.x; out[5] += r1.y; out[6] += r1.z; out[7] += r1.w;
        }
        *(float4*)(Y + (size_t)row * H + tc * 8) =
            make_float4(out[0], out[1], out[2], out[3]);
        *(float4*)(Y + (size_t)row * H + tc * 8 + 4) =
            make_float4(out[4], out[5], out[6], out[7]);
    }
}

// ---------------- per-node coord weight: wn = C1 . cW2 + cb2 ----------------
__global__ void wnode_kernel(const float* __restrict__ C1, const float* __restrict__ w2,
                             const float* __restrict__ b, float* __restrict__ wn, int n)
{
    int g = blockIdx.x * blockDim.x + threadIdx.x;
    int node = g >> 5, lane = g & 31;
    if (node >= n) return;
    float4 a = *(const float4*)(C1 + (size_t)node * H + lane * 4);
    float4 w = *(const float4*)(w2 + lane * 4);
    float s = a.x * w.x + a.y * w.y + a.z * w.z + a.w * w.w;
#pragma unroll
    for (int o = 16; o > 0; o >>= 1) s += __shfl_xor_sync(0xffffffffu, s, o);
    if (lane == 0) wn[node] = s + b[0];
}

// ---------------- fused edge kernel -----------------------------------------
// Per 64-edge tile: u = silu(A[dst]+B[src]+dist*W1c+b1); m = silu(u@W2+b2);
// atomic agg[dst] += m; atomic dpos[dst] += wnode[src]*rel/(dist+eps)
#define US 68
#define WSS 132
__global__ __launch_bounds__(128) void edge_kernel(
    const int* __restrict__ ei, int E, int Etot,
    const float* __restrict__ A, const float* __restrict__ B,
    const float* __restrict__ pos, const float* __restrict__ wnode,
    const float* __restrict__ W2, const float* __restrict__ b1,
    const float* __restrict__ b2, const float* __restrict__ w1c,
    float* __restrict__ agg, float* __restrict__ dpos)
{
    extern __shared__ float smbuf[];
    float* W2s = smbuf;                  // 128*132
    float* Us  = W2s + 128 * WSS;        // 128*68  (layout [k][e])
    float* srx = Us + 128 * US;
    float* sry = srx + 64;
    float* srz = sry + 64;
    float* sdist = srz + 64;
    int* ssrc = (int*)(sdist + 64);
    int* sdst = ssrc + 64;

    const int tid = threadIdx.x;
    const int tm = tid & 7, tc = tid >> 3;

    for (int q = tid; q < 128 * 32; q += 128) {
        int k = q >> 5, c4 = q & 31;
        *(float4*)(W2s + k * WSS + c4 * 4) = *(const float4*)(W2 + (size_t)k * H + c4 * 4);
    }
    const float w1ck = w1c[tid];
    const float b1k = b1[tid];
    float b2r[8];
#pragma unroll
    for (int j = 0; j < 8; j++) b2r[j] = b2[tc * 8 + j];
    __syncthreads();

    const int ntiles = (Etot + 63) >> 6;
    for (int tile = blockIdx.x; tile < ntiles; tile += gridDim.x) {
        const int e0 = tile << 6;
        const int cnt = min(64, Etot - e0);

        if (tid < 64) {
            int e = e0 + tid;
            int s = 0, d = 0; float rx = 0.f, ry = 0.f, rz = 0.f, dist = 0.f;
            if (tid < cnt) {
                if (e < E) { s = ei[e]; d = ei[E + e]; }
                else       { s = e - E; d = s; }
                rx = pos[s * 3 + 0] - pos[d * 3 + 0];
                ry = pos[s * 3 + 1] - pos[d * 3 + 1];
                rz = pos[s * 3 + 2] - pos[d * 3 + 2];
                dist = sqrtf(rx * rx + ry * ry + rz * rz);
            }
            ssrc[tid] = s; sdst[tid] = d;
            srx[tid] = rx; sry[tid] = ry; srz[tid] = rz; sdist[tid] = dist;
        }
        __syncthreads();

        // phase 1: u  (thread tid == feature k; coalesced 128B gathers)
        {
            const int k = tid;
            for (int e = 0; e < cnt; ++e) {
                int s = ssrc[e], d = sdst[e];
                float pre = A[(size_t)d * H + k] + B[(size_t)s * H + k]
                          + sdist[e] * w1ck + b1k;
                Us[k * US + e] = silu_f(pre);
            }
            for (int e = cnt; e < 64; ++e) Us[k * US + e] = 0.0f;
        }

        // coord update (meta only; runs while others fill u)
        if (tid < cnt) {
            float w = wnode[ssrc[tid]];
            float inv = w / (sdist[tid] + EPS);
            int d = sdst[tid];
            atomicAdd(dpos + d * 3 + 0, srx[tid] * inv);
            atomicAdd(dpos + d * 3 + 1, sry[tid] * inv);
            atomicAdd(dpos + d * 3 + 2, srz[tid] * inv);
        }
        __syncthreads();

        // phase 2: 64x128x128 GEMM (m = u @ W2)
        float acc[8][8];
#pragma unroll
        for (int i = 0; i < 8; i++)
#pragma unroll
            for (int j = 0; j < 8; j++) acc[i][j] = 0.0f;

#pragma unroll 8
        for (int k = 0; k < H; ++k) {
            float4 a0 = *(const float4*)(Us + k * US + tm * 8);
            float4 a1 = *(const float4*)(Us + k * US + tm * 8 + 4);
            float4 c0 = *(const float4*)(W2s + k * WSS + tc * 8);
            float4 c1 = *(const float4*)(W2s + k * WSS + tc * 8 + 4);
            float av[8] = {a0.x, a0.y, a0.z, a0.w, a1.x, a1.y, a1.z, a1.w};
            float bv[8] = {c0.x, c0.y, c0.z, c0.w, c1.x, c1.y, c1.z, c1.w};
#pragma unroll
            for (int i = 0; i < 8; i++)
#pragma unroll
                for (int j = 0; j < 8; j++)
                    acc[i][j] = fmaf(av[i], bv[j], acc[i][j]);
        }

        // phase 3: silu + scatter-add
#pragma unroll
        for (int i = 0; i < 8; i++) {
            int e = tm * 8 + i;
            if (e < cnt) {
                int d = sdst[e];
                float* base = agg + (size_t)d * H + tc * 8;
#pragma unroll
                for (int j = 0; j < 8; j++) {
                    float m = silu_f(acc[i][j] + b2r[j]);
                    atomicAdd(base + j, m);
                }
            }
        }
        __syncthreads();
    }
}

// ---------------- small utility kernels --------------------------------------
__global__ void zero_kernel(float* __restrict__ p, int n) {
    int i = blockIdx.x * blockDim.x + threadIdx.x;
    if (i < n) p[i] = 0.0f;
}
__global__ void copy_kernel(float* __restrict__ dst, const float* __restrict__ src, int n) {
    int i = blockIdx.x * blockDim.x + threadIdx.x;
    if (i < n) dst[i] = src[i];
}
__global__ void add_kernel(float* __restrict__ dst, const float* __restrict__ src, int n) {
    int i = blockIdx.x * blockDim.x + threadIdx.x;
    if (i < n) dst[i] += src[i];
}

// ---------------- host orchestration -----------------------------------------
extern "C" void kernel_launch(void* const* d_in, const int* in_sizes, int n_in,
                              void* d_out, int out_size)
{
    const float* h_in   = (const float*)d_in[0];
    const float* pos_in = (const float*)d_in[1];
    const int*   ei     = (const int*)d_in[2];
    const float* embW   = (const float*)d_in[3];
    const float* embB   = (const float*)d_in[4];
    const float* msgW1  = (const float*)d_in[5];
    const float* msgB1  = (const float*)d_in[6];
    const float* msgW2  = (const float*)d_in[7];
    const float* msgB2  = (const float*)d_in[8];
    const float* cW1    = (const float*)d_in[9];
    const float* cB1    = (const float*)d_in[10];
    const float* cW2    = (const float*)d_in[11];
    const float* cB2    = (const float*)d_in[12];
    const float* nW1    = (const float*)d_in[13];
    const float* nB1    = (const float*)d_in[14];
    const float* nW2    = (const float*)d_in[15];
    const float* nB2    = (const float*)d_in[16];
    const float* oW1    = (const float*)d_in[17];
    const float* oB1    = (const float*)d_in[18];
    const float* oW2    = (const float*)d_in[19];
    const float* oB2    = (const float*)d_in[20];

    const int N = in_sizes[1] / 3;
    const int E = in_sizes[2] / 2;
    const int Etot = E + N;
    const int INDIM = in_sizes[0] / N;

    float *bh, *bA, *bB, *bC1, *bagg, *bT, *bpos, *bdpos, *bwn;
    cudaGetSymbolAddress((void**)&bh, g_h);
    cudaGetSymbolAddress((void**)&bA, g_A);
    cudaGetSymbolAddress((void**)&bB, g_B);
    cudaGetSymbolAddress((void**)&bC1, g_C1);
    cudaGetSymbolAddress((void**)&bagg, g_agg);
    cudaGetSymbolAddress((void**)&bT, g_T);
    cudaGetSymbolAddress((void**)&bpos, g_pos);
    cudaGetSymbolAddress((void**)&bdpos, g_dpos);
    cudaGetSymbolAddress((void**)&bwn, g_wnode);

    const int EDGE_SMEM = (128 * WSS + 128 * US + 4 * 64) * 4 + 2 * 64 * 4;
    cudaFuncSetAttribute(edge_kernel,
                         cudaFuncAttributeMaxDynamicSharedMemorySize, EDGE_SMEM);

    const int gn = (N + 63) / 64;
    const int t256n = (N * H + 255) / 256;
    const int t256p = (N * 3 + 255) / 256;

    // h = h_in @ emb_W + emb_b
    node_gemm<<<gn, 128>>>(h_in, INDIM, nullptr, 0, embW, embB, nullptr, 0, bh, N);
    // pos working copy
    copy_kernel<<<t256p, 256>>>(bpos, pos_in, N * 3);

    for (int l = 0; l < LAYERS; ++l) {
        const float* W1a = msgW1 + (size_t)l * 257 * H;            // rows for h[dst]
        const float* W1b = W1a + 128 * H;                          // rows for h[src]
        const float* W1c = msgW1 + (size_t)l * 257 * H + 256 * H;  // dist row

        // coord scalar per node: wn = silu(h@cW1+cb1) . cW2 + cb2
        node_gemm<<<gn, 128>>>(bh, H, nullptr, 0, cW1 + (size_t)l * H * H,
                               cB1 + l * H, nullptr, 1, bC1, N);
        wnode_kernel<<<(N * 32 + 255) / 256, 256>>>(bC1, cW2 + (size_t)l * H,
                                                    cB2 + l, bwn, N);
        // per-node message halves
        node_gemm<<<gn, 128>>>(bh, H, nullptr, 0, W1a, nullptr, nullptr, 0, bA, N);
        node_gemm<<<gn, 128>>>(bh, H, nullptr, 0, W1b, nullptr, nullptr, 0, bB, N);

        zero_kernel<<<t256n, 256>>>(bagg, N * H);
        zero_kernel<<<t256p, 256>>>(bdpos, N * 3);

        edge_kernel<<<296, 128, EDGE_SMEM>>>(
            ei, E, Etot, bA, bB, bpos, bwn,
            msgW2 + (size_t)l * H * H, msgB1 + l * H, msgB2 + l * H, W1c,
            bagg, bdpos);

        // node update: h = h + silu([h,agg]@nW1+b1)@nW2+b2
        node_gemm<<<gn, 128>>>(bh, H, bagg, H, nW1 + (size_t)l * 2 * H * H,
                               nB1 + l * H, nullptr, 1, bT, N);
        node_gemm<<<gn, 128>>>(bT, H, nullptr, 0, nW2 + (size_t)l * H * H,
                               nB2 + l * H, bh, 0, bh, N);
        // pos += dpos
        add_kernel<<<t256p, 256>>>(bpos, bdpos, N * 3);
    }

    // out = silu(h@oW1+ob1)@oW2+ob2
    node_gemm<<<gn, 128>>>(bh, H, nullptr, 0, oW1, oB1, nullptr, 1, bT, N);
    node_gemm<<<gn, 128>>>(bT, H, nullptr, 0, oW2, oB2, nullptr, 0, (float*)d_out, N);

    // pos output, if the flattened tuple layout includes it
    if (out_size >= N * H + N * 3) {
        copy_kernel<<<t256p, 256>>>((float*)d_out + (size_t)N * H, bpos, N * 3);
    }
}

// round 2
// speedup vs baseline: 1.0778x; 1.0778x over previous
#include <cuda_runtime.h>
#include <math.h>

#define H 128
#define LAYERS 4
#define NMAX 50176
#define EPS 1e-8f

// ---------------- static device scratch (allocation-free rule) ----------------
__device__ float g_h[NMAX * H];
__device__ float g_A[NMAX * H];     // (h @ msgW1[0:128])   -> indexed by dst
__device__ float g_B[NMAX * H];     // (h @ msgW1[128:256]) -> indexed by src
__device__ float g_C1[NMAX * H];    // coord hidden
__device__ float g_agg[NMAX * H];   // message scatter target
__device__ float g_T[NMAX * H];     // generic temp
__device__ float g_pos[NMAX * 3];
__device__ float g_dpos[NMAX * 3];
__device__ float g_wnode[NMAX];

__device__ __forceinline__ float silu_f(float x) {
    return x / (1.0f + __expf(-x));
}

__device__ __forceinline__ void red_add_v4(float* addr, float a, float b, float c, float d) {
    asm volatile("red.global.add.v4.f32 [%0], {%1,%2,%3,%4};"
                 :: "l"(addr), "f"(a), "f"(b), "f"(c), "f"(d) : "memory");
}

// ---------------- node-side GEMM: Y = epi( [X1|X2] @ W + bias ) ---------------
// Tile 128 rows x 128 cols, 256 threads, 8x8 per thread. W row-major [Ktot,128].
__global__ __launch_bounds__(256) void node_gemm(
    const float* __restrict__ X1, int K1,
    const float* __restrict__ X2, int K2,
    const float* __restrict__ W,
    const float* __restrict__ bias,   // may be null
    const float* __restrict__ res,    // may be null (residual add AFTER act)
    int act,                          // 1 = silu
    float* __restrict__ Y, int n)
{
    __shared__ float Xs[16 * 132];
    __shared__ float Ws[16 * 132];
    const int tid = threadIdx.x;
    const int row0 = blockIdx.x * 128;
    const int tm = tid & 15;       // 16 row groups of 8
    const int tc = tid >> 4;       // 16 col groups of 8

    float acc[8][8];
#pragma unroll
    for (int i = 0; i < 8; i++)
#pragma unroll
        for (int j = 0; j < 8; j++) acc[i][j] = 0.0f;

    const int Ktot = K1 + K2;
    for (int kc = 0; kc < Ktot; kc += 16) {
        const float* src; int stride, col;
        if (kc < K1) { src = X1; stride = K1; col = kc; }
        else         { src = X2; stride = K2; col = kc - K1; }

        // X tile 128x16 -> transposed Xs[k][m]
#pragma unroll
        for (int q = tid; q < 512; q += 256) {
            int m = q >> 2, kq = q & 3;
            int row = row0 + m;
            float4 v = make_float4(0.f, 0.f, 0.f, 0.f);
            if (row < n) v = *(const float4*)(src + (size_t)row * stride + col + kq * 4);
            Xs[(kq * 4 + 0) * 132 + m] = v.x;
            Xs[(kq * 4 + 1) * 132 + m] = v.y;
            Xs[(kq * 4 + 2) * 132 + m] = v.z;
            Xs[(kq * 4 + 3) * 132 + m] = v.w;
        }
        // W tile 16x128
#pragma unroll
        for (int q = tid; q < 512; q += 256) {
            int k = q >> 5, c4 = q & 31;
            *(float4*)(Ws + k * 132 + c4 * 4) =
                *(const float4*)(W + (size_t)(kc + k) * H + c4 * 4);
        }
        __syncthreads();

#pragma unroll
        for (int k = 0; k < 16; ++k) {
            float4 a0 = *(const float4*)(Xs + k * 132 + tm * 8);
            float4 a1 = *(const float4*)(Xs + k * 132 + tm * 8 + 4);
            float4 b0 = *(const float4*)(Ws + k * 132 + tc * 8);
            float4 b1 = *(const float4*)(Ws + k * 132 + tc * 8 + 4);
            float av[8] = {a0.x, a0.y, a0.z, a0.w, a1.x, a1.y, a1.z, a1.w};
            float bv[8] = {b0.x, b0.y, b0.z, b0.w, b1.x, b1.y, b1.z, b1.w};
#pragma unroll
            for (int i = 0; i < 8; i++)
#pragma unroll
                for (int j = 0; j < 8; j++)
                    acc[i][j] = fmaf(av[i], bv[j], acc[i][j]);
        }
        __syncthreads();
    }

    float bb[8];
#pragma unroll
    for (int j = 0; j < 8; j++) bb[j] = bias ? bias[tc * 8 + j] : 0.0f;

#pragma unroll
    for (int i = 0; i < 8; i++) {
        int row = row0 + tm * 8 + i;
        if (row >= n) continue;
        float out[8];
#pragma unroll
        for (int j = 0; j < 8; j++) {
            float v = acc[i][j] + bb[j];
            if (act) v = silu_f(v);
            out[j] = v;
        }
        if (res) {
            float4 r0 = *(const float4*)(res + (size_t)row * H + tc * 8);
            float4 r1 = *(const float4*)(res + (size_t)row * H + tc * 8 + 4);
            out[0] += r0.x; out[1] += r0.y; out[2] += r0.z; out[3] += r0.w;
            out[4] += r1.x; out[5] += r1.y; out[6] += r1.z; out[7] += r1.w;
        }
        *(float4*)(Y + (size_t)row * H + tc * 8) =
            make_float4(out[0], out[1], out[2], out[3]);
        *(float4*)(Y + (size_t)row * H + tc * 8 + 4) =
            make_float4(out[4], out[5], out[6], out[7]);
    }
}

// ---------------- per-node coord weight: wn = C1 . cW2 + cb2 ----------------
__global__ void wnode_kernel(const float* __restrict__ C1, const float* __restrict__ w2,
                             const float* __restrict__ b, float* __restrict__ wn, int n)
{
    int g = blockIdx.x * blockDim.x + threadIdx.x;
    int node = g >> 5, lane = g & 31;
    if (node >= n) return;
    float4 a = *(const float4*)(C1 + (size_t)node * H + lane * 4);
    float4 w = *(const float4*)(w2 + lane * 4);
    float s = a.x * w.x + a.y * w.y + a.z * w.z + a.w * w.w;
#pragma unroll
    for (int o = 16; o > 0; o >>= 1) s += __shfl_xor_sync(0xffffffffu, s, o);
    if (lane == 0) wn[node] = s + b[0];
}

// ---------------- fused edge kernel -----------------------------------------
// Per 128-edge tile (256 threads):
//   meta: gather edge endpoints, rel, dist; coord-update atomics
//   u = silu(A[dst]+B[src]+dist*W1c+b1)  (smem, [k][e] layout)
//   m = silu(u @ W2 + b2)                 (128x128x128 reg-tiled GEMM)
//   agg[dst] += m                         (red.global.add.v4.f32)
#define TE 128
#define US2 132
#define WSS 132
__global__ __launch_bounds__(256) void edge_kernel(
    const int* __restrict__ ei, int E, int Etot,
    const float* __restrict__ A, const float* __restrict__ B,
    const float* __restrict__ pos, const float* __restrict__ wnode,
    const float* __restrict__ W2, const float* __restrict__ b1,
    const float* __restrict__ b2, const float* __restrict__ w1c,
    float* __restrict__ agg, float* __restrict__ dpos)
{
    extern __shared__ float smbuf[];
    float* W2s = smbuf;                  // 128*132
    float* Us  = W2s + 128 * WSS;        // 128*132  (layout [k][e])
    float* sdist = Us + 128 * US2;       // 128
    int* ssrc = (int*)(sdist + TE);      // 128
    int* sdst = ssrc + TE;               // 128

    const int tid = threadIdx.x;
    const int tm = tid & 15, tc = tid >> 4;

    // stage W2 once per block
#pragma unroll
    for (int q = tid; q < 128 * 32; q += 256) {
        int k = q >> 5, c4 = q & 31;
        *(float4*)(W2s + k * WSS + c4 * 4) = *(const float4*)(W2 + (size_t)k * H + c4 * 4);
    }
    const int kk = tid & 127;
    const float w1ck = w1c[kk];
    const float b1k = b1[kk];
    float b2r[8];
#pragma unroll
    for (int j = 0; j < 8; j++) b2r[j] = b2[tc * 8 + j];
    __syncthreads();

    const int ntiles = (Etot + TE - 1) / TE;
    for (int tile = blockIdx.x; tile < ntiles; tile += gridDim.x) {
        const int e0 = tile * TE;
        const int cnt = min(TE, Etot - e0);

        // ---- meta + coord update ----
        if (tid < TE) {
            int e = e0 + tid;
            int s = 0, d = 0; float dist = 0.f;
            if (tid < cnt) {
                float rx, ry, rz;
                if (e < E) { s = ei[e]; d = ei[E + e]; }
                else       { s = e - E; d = s; }
                rx = pos[s * 3 + 0] - pos[d * 3 + 0];
                ry = pos[s * 3 + 1] - pos[d * 3 + 1];
                rz = pos[s * 3 + 2] - pos[d * 3 + 2];
                dist = sqrtf(rx * rx + ry * ry + rz * rz);
                float inv = wnode[s] / (dist + EPS);
                atomicAdd(dpos + d * 3 + 0, rx * inv);
                atomicAdd(dpos + d * 3 + 1, ry * inv);
                atomicAdd(dpos + d * 3 + 2, rz * inv);
            }
            ssrc[tid] = s; sdst[tid] = d; sdist[tid] = dist;
        }
        __syncthreads();

        // ---- phase 1: u (feature k per thread-half, coalesced gathers) ----
        {
            const int eb = (tid >> 7) << 6;   // 0 or 64
            const float* Ak = A + kk;
            const float* Bk = B + kk;
            float* Urow = Us + kk * US2;
#pragma unroll 4
            for (int i = 0; i < 64; ++i) {
                int e = eb + i;
                int s = ssrc[e], d = sdst[e];
                float pre = __ldg(Ak + (size_t)d * H) + __ldg(Bk + (size_t)s * H)
                          + sdist[e] * w1ck + b1k;
                Urow[e] = silu_f(pre);
            }
        }
        __syncthreads();

        // ---- phase 2: 128x128x128 GEMM (m = u @ W2) ----
        float acc[8][8];
#pragma unroll
        for (int i = 0; i < 8; i++)
#pragma unroll
            for (int j = 0; j < 8; j++) acc[i][j] = 0.0f;

#pragma unroll 8
        for (int k = 0; k < H; ++k) {
            float4 a0 = *(const float4*)(Us + k * US2 + tm * 8);
            float4 a1 = *(const float4*)(Us + k * US2 + tm * 8 + 4);
            float4 c0 = *(const float4*)(W2s + k * WSS + tc * 8);
            float4 c1 = *(const float4*)(W2s + k * WSS + tc * 8 + 4);
            float av[8] = {a0.x, a0.y, a0.z, a0.w, a1.x, a1.y, a1.z, a1.w};
            float bv[8] = {c0.x, c0.y, c0.z, c0.w, c1.x, c1.y, c1.z, c1.w};
#pragma unroll
            for (int i = 0; i < 8; i++)
#pragma unroll
                for (int j = 0; j < 8; j++)
                    acc[i][j] = fmaf(av[i], bv[j], acc[i][j]);
        }

        // ---- phase 3: silu + vectorized scatter-add ----
#pragma unroll
        for (int i = 0; i < 8; i++) {
            int e = tm * 8 + i;
            if (e < cnt) {
                int d = sdst[e];
                float* base = agg + (size_t)d * H + tc * 8;
                float m0 = silu_f(acc[i][0] + b2r[0]);
                float m1 = silu_f(acc[i][1] + b2r[1]);
                float m2 = silu_f(acc[i][2] + b2r[2]);
                float m3 = silu_f(acc[i][3] + b2r[3]);
                red_add_v4(base, m0, m1, m2, m3);
                float m4 = silu_f(acc[i][4] + b2r[4]);
                float m5 = silu_f(acc[i][5] + b2r[5]);
                float m6 = silu_f(acc[i][6] + b2r[6]);
                float m7 = silu_f(acc[i][7] + b2r[7]);
                red_add_v4(base + 4, m4, m5, m6, m7);
            }
        }
        __syncthreads();
    }
}

// ---------------- small utility kernels --------------------------------------
__global__ void copy_kernel(float* __restrict__ dst, const float* __restrict__ src, int n) {
    int i = blockIdx.x * blockDim.x + threadIdx.x;
    if (i < n) dst[i] = src[i];
}
__global__ void add_kernel(float* __restrict__ dst, const float* __restrict__ src, int n) {
    int i = blockIdx.x * blockDim.x + threadIdx.x;
    if (i < n) dst[i] += src[i];
}

// ---------------- host orchestration -----------------------------------------
extern "C" void kernel_launch(void* const* d_in, const int* in_sizes, int n_in,
                              void* d_out, int out_size)
{
    const float* h_in   = (const float*)d_in[0];
    const float* pos_in = (const float*)d_in[1];
    const int*   ei     = (const int*)d_in[2];
    const float* embW   = (const float*)d_in[3];
    const float* embB   = (const float*)d_in[4];
    const float* msgW1  = (const float*)d_in[5];
    const float* msgB1  = (const float*)d_in[6];
    const float* msgW2  = (const float*)d_in[7];
    const float* msgB2  = (const float*)d_in[8];
    const float* cW1    = (const float*)d_in[9];
    const float* cB1    = (const float*)d_in[10];
    const float* cW2    = (const float*)d_in[11];
    const float* cB2    = (const float*)d_in[12];
    const float* nW1    = (const float*)d_in[13];
    const float* nB1    = (const float*)d_in[14];
    const float* nW2    = (const float*)d_in[15];
    const float* nB2    = (const float*)d_in[16];
    const float* oW1    = (const float*)d_in[17];
    const float* oB1    = (const float*)d_in[18];
    const float* oW2    = (const float*)d_in[19];
    const float* oB2    = (const float*)d_in[20];

    const int N = in_sizes[1] / 3;
    const int E = in_sizes[2] / 2;
    const int Etot = E + N;
    const int INDIM = in_sizes[0] / N;

    float *bh, *bA, *bB, *bC1, *bagg, *bT, *bpos, *bdpos, *bwn;
    cudaGetSymbolAddress((void**)&bh, g_h);
    cudaGetSymbolAddress((void**)&bA, g_A);
    cudaGetSymbolAddress((void**)&bB, g_B);
    cudaGetSymbolAddress((void**)&bC1, g_C1);
    cudaGetSymbolAddress((void**)&bagg, g_agg);
    cudaGetSymbolAddress((void**)&bT, g_T);
    cudaGetSymbolAddress((void**)&bpos, g_pos);
    cudaGetSymbolAddress((void**)&bdpos, g_dpos);
    cudaGetSymbolAddress((void**)&bwn, g_wnode);

    const int EDGE_SMEM = (128 * WSS + 128 * US2 + TE) * 4 + 2 * TE * 4;
    cudaFuncSetAttribute(edge_kernel,
                         cudaFuncAttributeMaxDynamicSharedMemorySize, EDGE_SMEM);

    const int gn = (N + 127) / 128;
    const int t256p = (N * 3 + 255) / 256;

    // h = h_in @ emb_W + emb_b
    node_gemm<<<gn, 256>>>(h_in, INDIM, nullptr, 0, embW, embB, nullptr, 0, bh, N);
    // pos working copy
    copy_kernel<<<t256p, 256>>>(bpos, pos_in, N * 3);

    for (int l = 0; l < LAYERS; ++l) {
        const float* W1a = msgW1 + (size_t)l * 257 * H;            // rows for h[dst]
        const float* W1b = W1a + 128 * H;                          // rows for h[src]
        const float* W1c = msgW1 + (size_t)l * 257 * H + 256 * H;  // dist row

        // coord scalar per node: wn = silu(h@cW1+cb1) . cW2 + cb2
        node_gemm<<<gn, 256>>>(bh, H, nullptr, 0, cW1 + (size_t)l * H * H,
                               cB1 + l * H, nullptr, 1, bC1, N);
        wnode_kernel<<<(N * 32 + 255) / 256, 256>>>(bC1, cW2 + (size_t)l * H,
                                                    cB2 + l, bwn, N);
        // per-node message halves
        node_gemm<<<gn, 256>>>(bh, H, nullptr, 0, W1a, nullptr, nullptr, 0, bA, N);
        node_gemm<<<gn, 256>>>(bh, H, nullptr, 0, W1b, nullptr, nullptr, 0, bB, N);

        cudaMemsetAsync(bagg, 0, (size_t)N * H * sizeof(float));
        cudaMemsetAsync(bdpos, 0, (size_t)N * 3 * sizeof(float));

        edge_kernel<<<148, 256, EDGE_SMEM>>>(
            ei, E, Etot, bA, bB, bpos, bwn,
            msgW2 + (size_t)l * H * H, msgB1 + l * H, msgB2 + l * H, W1c,
            bagg, bdpos);

        // node update: h = h + silu([h,agg]@nW1+b1)@nW2+b2
        node_gemm<<<gn, 256>>>(bh, H, bagg, H, nW1 + (size_t)l * 2 * H * H,
                               nB1 + l * H, nullptr, 1, bT, N);
        node_gemm<<<gn, 256>>>(bT, H, nullptr, 0, nW2 + (size_t)l * H * H,
                               nB2 + l * H, bh, 0, bh, N);
        // pos += dpos
        add_kernel<<<t256p, 256>>>(bpos, bdpos, N * 3);
    }

    // out = silu(h@oW1+ob1)@oW2+ob2
    node_gemm<<<gn, 256>>>(bh, H, nullptr, 0, oW1, oB1, nullptr, 1, bT, N);
    node_gemm<<<gn, 256>>>(bT, H, nullptr, 0, oW2, oB2, nullptr, 0, (float*)d_out, N);

    // pos output, if the flattened tuple layout includes it
    if (out_size >= N * H + N * 3) {
        copy_kernel<<<t256p, 256>>>((float*)d_out + (size_t)N * H, bpos, N * 3);
    }
}

// round 3
// speedup vs baseline: 1.1547x; 1.0714x over previous
#include <cuda_runtime.h>
#include <math.h>

#define H 128
#define LAYERS 4
#define NMAX 50176
#define EPS 1e-8f

// ---------------- static device scratch (allocation-free rule) ----------------
__device__ float g_h[NMAX * H];
__device__ float g_A[NMAX * H];     // (h @ msgW1[0:128])   -> indexed by dst
__device__ float g_B[NMAX * H];     // (h @ msgW1[128:256]) -> indexed by src
__device__ float g_C1[NMAX * H];    // coord hidden
__device__ float g_agg[NMAX * H];   // message scatter target
__device__ float g_T[NMAX * H];     // generic temp
__device__ float g_pos[NMAX * 3];
__device__ float g_dpos[NMAX * 3];
__device__ float g_wnode[NMAX];

__device__ __forceinline__ float silu_f(float x) {
    return x / (1.0f + __expf(-x));
}

__device__ __forceinline__ void red_add_v4(float* addr, float a, float b, float c, float d) {
    asm volatile("red.global.add.v4.f32 [%0], {%1,%2,%3,%4};"
                 :: "l"(addr), "f"(a), "f"(b), "f"(c), "f"(d) : "memory");
}

// ---------------- shared 128x128 GEMM tile body (256 threads) -----------------
// Y[row0:row0+128, 0:128] = epi( [X1|X2](rows) @ W + bias ), optional residual.
__device__ __forceinline__ void gemm_tile_body(
    const float* __restrict__ X1, int K1,
    const float* __restrict__ X2, int K2,
    const float* __restrict__ W,
    const float* __restrict__ bias,
    const float* __restrict__ res,
    int act,
    float* __restrict__ Y, int n, int row0,
    float* Xs, float* Ws)
{
    const int tid = threadIdx.x;
    const int tm = tid & 15;
    const int tc = tid >> 4;

    float acc[8][8];
#pragma unroll
    for (int i = 0; i < 8; i++)
#pragma unroll
        for (int j = 0; j < 8; j++) acc[i][j] = 0.0f;

    const int Ktot = K1 + K2;
    for (int kc = 0; kc < Ktot; kc += 16) {
        const float* src; int stride, col;
        if (kc < K1) { src = X1; stride = K1; col = kc; }
        else         { src = X2; stride = K2; col = kc - K1; }

#pragma unroll
        for (int q = tid; q < 512; q += 256) {
            int m = q >> 2, kq = q & 3;
            int row = row0 + m;
            float4 v = make_float4(0.f, 0.f, 0.f, 0.f);
            if (row < n) v = *(const float4*)(src + (size_t)row * stride + col + kq * 4);
            Xs[(kq * 4 + 0) * 132 + m] = v.x;
            Xs[(kq * 4 + 1) * 132 + m] = v.y;
            Xs[(kq * 4 + 2) * 132 + m] = v.z;
            Xs[(kq * 4 + 3) * 132 + m] = v.w;
        }
#pragma unroll
        for (int q = tid; q < 512; q += 256) {
            int k = q >> 5, c4 = q & 31;
            *(float4*)(Ws + k * 132 + c4 * 4) =
                *(const float4*)(W + (size_t)(kc + k) * H + c4 * 4);
        }
        __syncthreads();

#pragma unroll
        for (int k = 0; k < 16; ++k) {
            float4 a0 = *(const float4*)(Xs + k * 132 + tm * 8);
            float4 a1 = *(const float4*)(Xs + k * 132 + tm * 8 + 4);
            float4 b0 = *(const float4*)(Ws + k * 132 + tc * 8);
            float4 b1 = *(const float4*)(Ws + k * 132 + tc * 8 + 4);
            float av[8] = {a0.x, a0.y, a0.z, a0.w, a1.x, a1.y, a1.z, a1.w};
            float bv[8] = {b0.x, b0.y, b0.z, b0.w, b1.x, b1.y, b1.z, b1.w};
#pragma unroll
            for (int i = 0; i < 8; i++)
#pragma unroll
                for (int j = 0; j < 8; j++)
                    acc[i][j] = fmaf(av[i], bv[j], acc[i][j]);
        }
        __syncthreads();
    }

    float bb[8];
#pragma unroll
    for (int j = 0; j < 8; j++) bb[j] = bias ? bias[tc * 8 + j] : 0.0f;

#pragma unroll
    for (int i = 0; i < 8; i++) {
        int row = row0 + tm * 8 + i;
        if (row >= n) continue;
        float out[8];
#pragma unroll
        for (int j = 0; j < 8; j++) {
            float v = acc[i][j] + bb[j];
            if (act) v = silu_f(v);
            out[j] = v;
        }
        if (res) {
            float4 r0 = *(const float4*)(res + (size_t)row * H + tc * 8);
            float4 r1 = *(const float4*)(res + (size_t)row * H + tc * 8 + 4);
            out[0] += r0.x; out[1] += r0.y; out[2] += r0.z; out[3] += r0.w;
            out[4] += r1.x; out[5] += r1.y; out[6] += r1.z; out[7] += r1.w;
        }
        *(float4*)(Y + (size_t)row * H + tc * 8) =
            make_float4(out[0], out[1], out[2], out[3]);
        *(float4*)(Y + (size_t)row * H + tc * 8 + 4) =
            make_float4(out[4], out[5], out[6], out[7]);
    }
}

__global__ __launch_bounds__(256) void node_gemm(
    const float* __restrict__ X1, int K1,
    const float* __restrict__ X2, int K2,
    const float* __restrict__ W,
    const float* __restrict__ bias,
    const float* __restrict__ res,
    int act,
    float* __restrict__ Y, int n)
{
    __shared__ float Xs[16 * 132];
    __shared__ float Ws[16 * 132];
    gemm_tile_body(X1, K1, X2, K2, W, bias, res, act, Y, n, blockIdx.x * 128, Xs, Ws);
}

// one launch computing C1 = silu(h@cW1+cb1), A = h@W1a, B = h@W1b
__global__ __launch_bounds__(256) void fused3_gemm(
    const float* __restrict__ hbuf,
    const float* __restrict__ cW1, const float* __restrict__ cB1,
    const float* __restrict__ W1a, const float* __restrict__ W1b,
    float* __restrict__ C1, float* __restrict__ A, float* __restrict__ B, int n)
{
    __shared__ float Xs[16 * 132];
    __shared__ float Ws[16 * 132];
    const float* W; const float* bias; float* Y; int act;
    if (blockIdx.y == 0)      { W = cW1; bias = cB1;    Y = C1; act = 1; }
    else if (blockIdx.y == 1) { W = W1a; bias = nullptr; Y = A;  act = 0; }
    else                      { W = W1b; bias = nullptr; Y = B;  act = 0; }
    gemm_tile_body(hbuf, H, nullptr, 0, W, bias, nullptr, act, Y, n, blockIdx.x * 128, Xs, Ws);
}

// ---------------- per-node coord weight: wn = C1 . cW2 + cb2 ----------------
__global__ void wnode_kernel(const float* __restrict__ C1, const float* __restrict__ w2,
                             const float* __restrict__ b, float* __restrict__ wn, int n)
{
    int g = blockIdx.x * blockDim.x + threadIdx.x;
    int node = g >> 5, lane = g & 31;
    if (node >= n) return;
    float4 a = *(const float4*)(C1 + (size_t)node * H + lane * 4);
    float4 w = *(const float4*)(w2 + lane * 4);
    float s = a.x * w.x + a.y * w.y + a.z * w.z + a.w * w.w;
#pragma unroll
    for (int o = 16; o > 0; o >>= 1) s += __shfl_xor_sync(0xffffffffu, s, o);
    if (lane == 0) wn[node] = s + b[0];
}

// ---------------- fused edge kernel (512 threads) ----------------------------
// Per 128-edge tile:
//   meta: endpoints, rel, dist; coord-update atomics
//   u = silu(A[dst]+B[src]+dist*W1c+b1)  (smem [k][e])
//   m = silu(u @ W2 + b2)                 (128x128x128 reg-tiled GEMM)
//   agg[dst] += m                         (red.global.add.v4.f32)
#define TE 128
#define US2 132
__global__ __launch_bounds__(512) void edge_kernel(
    const int* __restrict__ ei, int E, int Etot,
    const float* __restrict__ A, const float* __restrict__ B,
    const float* __restrict__ pos, const float* __restrict__ wnode,
    const float* __restrict__ W2, const float* __restrict__ b1,
    const float* __restrict__ b2, const float* __restrict__ w1c,
    float* __restrict__ agg, float* __restrict__ dpos)
{
    extern __shared__ float smbuf[];
    float* W2s = smbuf;                  // 128*132
    float* Us  = W2s + 128 * US2;        // 128*132  (layout [k][e])
    float* sdist = Us + 128 * US2;       // 128
    int* ssrc = (int*)(sdist + TE);      // 128
    int* sdst = ssrc + TE;               // 128

    const int tid = threadIdx.x;
    const int tm = tid & 15;             // edge group of 8
    const int tc = tid >> 4;             // 0..31, col group of 4

    // stage W2 once per block
#pragma unroll
    for (int q = tid; q < 128 * 32; q += 512) {
        int k = q >> 5, c4 = q & 31;
        *(float4*)(W2s + k * US2 + c4 * 4) = *(const float4*)(W2 + (size_t)k * H + c4 * 4);
    }
    const int kk = tid & 127;
    const float w1ck = w1c[kk];
    const float b1k = b1[kk];
    float b2r[4];
#pragma unroll
    for (int j = 0; j < 4; j++) b2r[j] = b2[tc * 4 + j];
    __syncthreads();

    const int ntiles = (Etot + TE - 1) / TE;
    for (int tile = blockIdx.x; tile < ntiles; tile += gridDim.x) {
        const int e0 = tile * TE;
        const int cnt = min(TE, Etot - e0);

        // ---- meta + coord update ----
        if (tid < TE) {
            int e = e0 + tid;
            int s = 0, d = 0; float dist = 0.f;
            if (tid < cnt) {
                float rx, ry, rz;
                if (e < E) { s = ei[e]; d = ei[E + e]; }
                else       { s = e - E; d = s; }
                rx = pos[s * 3 + 0] - pos[d * 3 + 0];
                ry = pos[s * 3 + 1] - pos[d * 3 + 1];
                rz = pos[s * 3 + 2] - pos[d * 3 + 2];
                dist = sqrtf(rx * rx + ry * ry + rz * rz);
                float inv = wnode[s] / (dist + EPS);
                atomicAdd(dpos + d * 3 + 0, rx * inv);
                atomicAdd(dpos + d * 3 + 1, ry * inv);
                atomicAdd(dpos + d * 3 + 2, rz * inv);
            }
            ssrc[tid] = s; sdst[tid] = d; sdist[tid] = dist;
        }
        __syncthreads();

        // ---- phase 1: u (feature kk, edge quarter q; coalesced gathers) ----
        {
            const int q = tid >> 7;          // 0..3 -> 32 edges each
            const int eb = q * 32;
            const float* Ak = A + kk;
            const float* Bk = B + kk;
            float* Urow = Us + kk * US2;
#pragma unroll 8
            for (int i = 0; i < 32; ++i) {
                int e = eb + i;
                int s = ssrc[e], d = sdst[e];
                float pre = __ldg(Ak + (size_t)d * H) + __ldg(Bk + (size_t)s * H)
                          + sdist[e] * w1ck + b1k;
                Urow[e] = silu_f(pre);
            }
        }
        __syncthreads();

        // ---- phase 2: 128x128x128 GEMM (m = u @ W2), 8x4 per thread ----
        float acc[8][4];
#pragma unroll
        for (int i = 0; i < 8; i++)
#pragma unroll
            for (int j = 0; j < 4; j++) acc[i][j] = 0.0f;

#pragma unroll 8
        for (int k = 0; k < H; ++k) {
            float4 a0 = *(const float4*)(Us + k * US2 + tm * 8);
            float4 a1 = *(const float4*)(Us + k * US2 + tm * 8 + 4);
            float4 c0 = *(const float4*)(W2s + k * US2 + tc * 4);
            float av[8] = {a0.x, a0.y, a0.z, a0.w, a1.x, a1.y, a1.z, a1.w};
            float bv[4] = {c0.x, c0.y, c0.z, c0.w};
#pragma unroll
            for (int i = 0; i < 8; i++)
#pragma unroll
                for (int j = 0; j < 4; j++)
                    acc[i][j] = fmaf(av[i], bv[j], acc[i][j]);
        }

        // ---- phase 3: silu + vectorized scatter-add ----
#pragma unroll
        for (int i = 0; i < 8; i++) {
            int e = tm * 8 + i;
            if (e < cnt) {
                int d = sdst[e];
                float m0 = silu_f(acc[i][0] + b2r[0]);
                float m1 = silu_f(acc[i][1] + b2r[1]);
                float m2 = silu_f(acc[i][2] + b2r[2]);
                float m3 = silu_f(acc[i][3] + b2r[3]);
                red_add_v4(agg + (size_t)d * H + tc * 4, m0, m1, m2, m3);
            }
        }
        __syncthreads();
    }
}

// ---------------- small utility kernels --------------------------------------
__global__ void copy_kernel(float* __restrict__ dst, const float* __restrict__ src, int n) {
    int i = blockIdx.x * blockDim.x + threadIdx.x;
    if (i < n) dst[i] = src[i];
}
__global__ void add_kernel(float* __restrict__ dst, const float* __restrict__ src, int n) {
    int i = blockIdx.x * blockDim.x + threadIdx.x;
    if (i < n) dst[i] += src[i];
}
__global__ void zero2_kernel(float* __restrict__ a, int n1, float* __restrict__ b, int n2) {
    int i = blockIdx.x * blockDim.x + threadIdx.x;
    if (i < n1) a[i] = 0.0f;
    else if (i - n1 < n2) b[i - n1] = 0.0f;
}

// ---------------- host orchestration -----------------------------------------
extern "C" void kernel_launch(void* const* d_in, const int* in_sizes, int n_in,
                              void* d_out, int out_size)
{
    const float* h_in   = (const float*)d_in[0];
    const float* pos_in = (const float*)d_in[1];
    const int*   ei     = (const int*)d_in[2];
    const float* embW   = (const float*)d_in[3];
    const float* embB   = (const float*)d_in[4];
    const float* msgW1  = (const float*)d_in[5];
    const float* msgB1  = (const float*)d_in[6];
    const float* msgW2  = (const float*)d_in[7];
    const float* msgB2  = (const float*)d_in[8];
    const float* cW1    = (const float*)d_in[9];
    const float* cB1    = (const float*)d_in[10];
    const float* cW2    = (const float*)d_in[11];
    const float* cB2    = (const float*)d_in[12];
    const float* nW1    = (const float*)d_in[13];
    const float* nB1    = (const float*)d_in[14];
    const float* nW2    = (const float*)d_in[15];
    const float* nB2    = (const float*)d_in[16];
    const float* oW1    = (const float*)d_in[17];
    const float* oB1    = (const float*)d_in[18];
    const float* oW2    = (const float*)d_in[19];
    const float* oB2    = (const float*)d_in[20];

    const int N = in_sizes[1] / 3;
    const int E = in_sizes[2] / 2;
    const int Etot = E + N;
    const int INDIM = in_sizes[0] / N;

    float *bh, *bA, *bB, *bC1, *bagg, *bT, *bpos, *bdpos, *bwn;
    cudaGetSymbolAddress((void**)&bh, g_h);
    cudaGetSymbolAddress((void**)&bA, g_A);
    cudaGetSymbolAddress((void**)&bB, g_B);
    cudaGetSymbolAddress((void**)&bC1, g_C1);
    cudaGetSymbolAddress((void**)&bagg, g_agg);
    cudaGetSymbolAddress((void**)&bT, g_T);
    cudaGetSymbolAddress((void**)&bpos, g_pos);
    cudaGetSymbolAddress((void**)&bdpos, g_dpos);
    cudaGetSymbolAddress((void**)&bwn, g_wnode);

    const int EDGE_SMEM = (128 * US2 * 2 + TE) * 4 + 2 * TE * 4;
    cudaFuncSetAttribute(edge_kernel,
                         cudaFuncAttributeMaxDynamicSharedMemorySize, EDGE_SMEM);

    const int gn = (N + 127) / 128;
    const int t256p = (N * 3 + 255) / 256;
    const int nz = N * H + N * 3;

    // launch 0: h = h_in @ emb_W + emb_b
    node_gemm<<<gn, 256>>>(h_in, INDIM, nullptr, 0, embW, embB, nullptr, 0, bh, N);
    // launch 1: pos working copy
    copy_kernel<<<t256p, 256>>>(bpos, pos_in, N * 3);

    for (int l = 0; l < LAYERS; ++l) {
        const float* W1a = msgW1 + (size_t)l * 257 * H;            // rows for h[dst]
        const float* W1b = W1a + 128 * H;                          // rows for h[src]
        const float* W1c = msgW1 + (size_t)l * 257 * H + 256 * H;  // dist row

        // launch 2 (layer 0): C1 / A / B in one shot
        fused3_gemm<<<dim3(gn, 3), 256>>>(bh, cW1 + (size_t)l * H * H, cB1 + l * H,
                                          W1a, W1b, bC1, bA, bB, N);
        // launch 3: per-node coord scalar
        wnode_kernel<<<(N * 32 + 255) / 256, 256>>>(bC1, cW2 + (size_t)l * H,
                                                    cB2 + l, bwn, N);
        // launch 4: zero agg + dpos
        zero2_kernel<<<(nz + 255) / 256, 256>>>(bagg, N * H, bdpos, N * 3);

        // launch 5 (layer 0): the edge kernel  -> ncu -s 5 -c 1 captures THIS
        edge_kernel<<<148, 512, EDGE_SMEM>>>(
            ei, E, Etot, bA, bB, bpos, bwn,
            msgW2 + (size_t)l * H * H, msgB1 + l * H, msgB2 + l * H, W1c,
            bagg, bdpos);

        // node update: h = h + silu([h,agg]@nW1+b1)@nW2+b2
        node_gemm<<<gn, 256>>>(bh, H, bagg, H, nW1 + (size_t)l * 2 * H * H,
                               nB1 + l * H, nullptr, 1, bT, N);
        node_gemm<<<gn, 256>>>(bT, H, nullptr, 0, nW2 + (size_t)l * H * H,
                               nB2 + l * H, bh, 0, bh, N);
        // pos += dpos
        add_kernel<<<t256p, 256>>>(bpos, bdpos, N * 3);
    }

    // out = silu(h@oW1+ob1)@oW2+ob2
    node_gemm<<<gn, 256>>>(bh, H, nullptr, 0, oW1, oB1, nullptr, 1, bT, N);
    node_gemm<<<gn, 256>>>(bT, H, nullptr, 0, oW2, oB2, nullptr, 0, (float*)d_out, N);

    // pos output
    if (out_size >= N * H + N * 3) {
        copy_kernel<<<t256p, 256>>>((float*)d_out + (size_t)N * H, bpos, N * 3);
    }
}

// round 4
// speedup vs baseline: 2.1002x; 1.8188x over previous
#include <cuda_runtime.h>
#include <math.h>

#define H 128
#define LAYERS 4
#define NMAX 50176
#define EPS 1e-8f
#define FR 136   // fragment-pack stride in floats (128 + 8 pad)

// ---------------- static device scratch (allocation-free rule) ----------------
__device__ float g_h[NMAX * H];
__device__ float g_A[NMAX * H];     // (h @ msgW1[0:128])   -> indexed by dst
__device__ float g_B[NMAX * H];     // (h @ msgW1[128:256]) -> indexed by src
__device__ float g_C1[NMAX * H];    // coord hidden
__device__ float g_agg[NMAX * H];   // message scatter target
__device__ float g_T[NMAX * H];     // generic temp
__device__ float g_pos[NMAX * 3];
__device__ float g_dpos[NMAX * 3];
__device__ float g_wnode[NMAX];

__device__ __forceinline__ float silu_f(float x) {
    return x / (1.0f + __expf(-x));
}

__device__ __forceinline__ unsigned f2tf(float x) {
    unsigned r;
    asm("cvt.rna.tf32.f32 %0, %1;" : "=r"(r) : "f"(x));
    return r;
}

__device__ __forceinline__ void mma_tf32(float c[4], const unsigned a[4], const unsigned b[2]) {
    asm volatile(
        "mma.sync.aligned.m16n8k8.row.col.f32.tf32.tf32.f32 "
        "{%0,%1,%2,%3}, {%4,%5,%6,%7}, {%8,%9}, {%0,%1,%2,%3};"
        : "+f"(c[0]), "+f"(c[1]), "+f"(c[2]), "+f"(c[3])
        : "r"(a[0]), "r"(a[1]), "r"(a[2]), "r"(a[3]), "r"(b[0]), "r"(b[1]));
}

__device__ __forceinline__ void red_add_v2(float* addr, float a, float b) {
    asm volatile("red.global.add.v2.f32 [%0], {%1,%2};"
                 :: "l"(addr), "f"(a), "f"(b) : "memory");
}

// fragment-packed smem address for element (row r in 0..127, k in 0..127):
//   frag = (r>>4)*16 + (k>>3); lane = (r&7)*4 + (k&3); slot = ((r>>3)&1) + 2*((k>>2)&1)
__device__ __forceinline__ int fp_addr(int r, int k) {
    return ((r >> 4) * 16 + (k >> 3)) * FR + ((r & 7) * 4 + (k & 3)) * 4
         + ((r >> 3) & 1) + 2 * ((k >> 2) & 1);
}

// ---------------- node-side GEMM (tf32 mma), 512 threads ----------------------
// one K-chunk: stage X into frag-packed smem, load B frags, accumulate.
template <int KS>   // k-steps in this chunk (8 or 16); kchunk = KS*8
__device__ __forceinline__ void node_chunk(
    const float* __restrict__ src, int stride, int coff, int kc,
    const float* __restrict__ W,
    float (&d)[4][2][4], float* Xs, int n, int row0)
{
    const int tid = threadIdx.x;
    const int lane = tid & 31;
    const int warp = tid >> 5;
    const int we = warp >> 3;
    const int wn = warp & 7;
    const int g = lane >> 2, t = lane & 3;

    __syncthreads();   // previous chunk's reads done
    // stage X (rows of this 128-row tile, kchunk cols) with tf32 cvt
    constexpr int Q4 = KS * 2;           // float4 per row
#pragma unroll
    for (int q = tid; q < 128 * Q4; q += 512) {
        int r = q / Q4;
        int kq = (q - r * Q4) << 2;
        int row = row0 + r;
        float4 v = make_float4(0.f, 0.f, 0.f, 0.f);
        if (row < n) v = *(const float4*)(src + (size_t)row * stride + coff + kq);
        float vv[4] = {v.x, v.y, v.z, v.w};
#pragma unroll
        for (int s2 = 0; s2 < 4; ++s2)
            Xs[fp_addr(r, kq + s2)] = __uint_as_float(f2tf(vv[s2]));
    }
    // B fragments in registers (2 n-tiles x KS k-steps x 2)
    unsigned bfr[2][KS][2];
#pragma unroll
    for (int j = 0; j < 2; ++j) {
        const int ncol = wn * 16 + j * 8 + g;
#pragma unroll
        for (int kk = 0; kk < KS; ++kk) {
            bfr[j][kk][0] = f2tf(__ldg(W + (size_t)(kc + kk * 8 + t) * H + ncol));
            bfr[j][kk][1] = f2tf(__ldg(W + (size_t)(kc + kk * 8 + t + 4) * H + ncol));
        }
    }
    __syncthreads();

#pragma unroll
    for (int i = 0; i < 4; ++i) {
        const float* ub = Xs + ((we * 4 + i) * 16) * FR + lane * 4;
#pragma unroll
        for (int kk = 0; kk < KS; ++kk) {
            float4 av = *(const float4*)(ub + kk * FR);
            unsigned a[4] = {__float_as_uint(av.x), __float_as_uint(av.y),
                             __float_as_uint(av.z), __float_as_uint(av.w)};
            mma_tf32(d[i][0], a, bfr[0][kk]);
            mma_tf32(d[i][1], a, bfr[1][kk]);
        }
    }
}

__device__ __forceinline__ void gemm_body_mma(
    const float* __restrict__ X1, int K1,
    const float* __restrict__ X2, int K2,
    const float* __restrict__ W,
    const float* __restrict__ bias,
    const float* __restrict__ res,
    int act,
    float* __restrict__ Y, int n, int row0, float* Xs)
{
    const int tid = threadIdx.x;
    const int lane = tid & 31;
    const int warp = tid >> 5;
    const int we = warp >> 3;
    const int wn = warp & 7;
    const int g = lane >> 2, t = lane & 3;

    float d[4][2][4];
#pragma unroll
    for (int i = 0; i < 4; ++i)
#pragma unroll
        for (int j = 0; j < 2; ++j)
#pragma unroll
            for (int s = 0; s < 4; ++s) d[i][j][s] = 0.0f;

    const int Ktot = K1 + K2;
    for (int kc = 0; kc < Ktot; kc += 128) {
        const int kchunk = min(128, Ktot - kc);
        const float* src; int stride, coff;
        if (kc < K1) { src = X1; stride = K1; coff = kc; }
        else         { src = X2; stride = K2; coff = kc - K1; }
        if (kchunk == 128) node_chunk<16>(src, stride, coff, kc, W, d, Xs, n, row0);
        else               node_chunk<8>(src, stride, coff, kc, W, d, Xs, n, row0);
    }

    // epilogue: 2-wide stores, bias/silu/residual
#pragma unroll
    for (int j = 0; j < 2; ++j) {
        const int col = wn * 16 + j * 8 + t * 2;
        float b0 = bias ? bias[col] : 0.0f;
        float b1v = bias ? bias[col + 1] : 0.0f;
#pragma unroll
        for (int i = 0; i < 4; ++i) {
            int rb = row0 + (we * 4 + i) * 16 + g;
#pragma unroll
            for (int half = 0; half < 2; ++half) {
                int row = rb + half * 8;
                if (row < n) {
                    float o0 = d[i][j][half * 2 + 0] + b0;
                    float o1 = d[i][j][half * 2 + 1] + b1v;
                    if (act) { o0 = silu_f(o0); o1 = silu_f(o1); }
                    if (res) {
                        o0 += res[(size_t)row * H + col];
                        o1 += res[(size_t)row * H + col + 1];
                    }
                    *(float2*)(Y + (size_t)row * H + col) = make_float2(o0, o1);
                }
            }
        }
    }
}

__global__ __launch_bounds__(512) void node_gemm(
    const float* __restrict__ X1, int K1,
    const float* __restrict__ X2, int K2,
    const float* __restrict__ W,
    const float* __restrict__ bias,
    const float* __restrict__ res,
    int act,
    float* __restrict__ Y, int n)
{
    extern __shared__ float Xs[];
    gemm_body_mma(X1, K1, X2, K2, W, bias, res, act, Y, n, blockIdx.x * 128, Xs);
}

// one launch computing C1 = silu(h@cW1+cb1), A = h@W1a, B = h@W1b
__global__ __launch_bounds__(512) void fused3_gemm(
    const float* __restrict__ hbuf,
    const float* __restrict__ cW1, const float* __restrict__ cB1,
    const float* __restrict__ W1a, const float* __restrict__ W1b,
    float* __restrict__ C1, float* __restrict__ A, float* __restrict__ B, int n)
{
    extern __shared__ float Xs[];
    const float* W; const float* bias; float* Y; int act;
    if (blockIdx.y == 0)      { W = cW1; bias = cB1;    Y = C1; act = 1; }
    else if (blockIdx.y == 1) { W = W1a; bias = nullptr; Y = A;  act = 0; }
    else                      { W = W1b; bias = nullptr; Y = B;  act = 0; }
    gemm_body_mma(hbuf, H, nullptr, 0, W, bias, nullptr, act, Y, n, blockIdx.x * 128, Xs);
}

// ---------------- per-node coord weight: wn = C1 . cW2 + cb2 ----------------
__global__ void wnode_kernel(const float* __restrict__ C1, const float* __restrict__ w2,
                             const float* __restrict__ b, float* __restrict__ wn, int n)
{
    int gidx = blockIdx.x * blockDim.x + threadIdx.x;
    int node = gidx >> 5, lane = gidx & 31;
    if (node >= n) return;
    float4 a = *(const float4*)(C1 + (size_t)node * H + lane * 4);
    float4 w = *(const float4*)(w2 + lane * 4);
    float s = a.x * w.x + a.y * w.y + a.z * w.z + a.w * w.w;
#pragma unroll
    for (int o = 16; o > 0; o >>= 1) s += __shfl_xor_sync(0xffffffffu, s, o);
    if (lane == 0) wn[node] = s + b[0];
}

// ---------------- fused edge kernel (tf32 mma, 512 threads) -------------------
// Per 128-edge tile:
//   meta: endpoints, dist; coord-update atomics
//   u = silu(A[dst]+B[src]+dist*W1c+b1)     written frag-packed (tf32 bits)
//   m = silu(u @ W2 + b2) via mma.sync       (B frags of W2 in registers)
//   agg[dst] += m                            (red.global.add.v2.f32)
#define TE 128
__global__ __launch_bounds__(512) void edge_kernel(
    const int* __restrict__ ei, int E, int Etot,
    const float* __restrict__ A, const float* __restrict__ B,
    const float* __restrict__ pos, const float* __restrict__ wnode,
    const float* __restrict__ W2, const float* __restrict__ b1,
    const float* __restrict__ b2, const float* __restrict__ w1c,
    float* __restrict__ agg, float* __restrict__ dpos)
{
    extern __shared__ float smbuf[];
    float* U = smbuf;                    // 128 frags * FR floats
    float* sdist = U + 128 * FR;         // 128
    int* ssrc = (int*)(sdist + TE);      // 128
    int* sdst = ssrc + TE;               // 128

    const int tid = threadIdx.x;
    const int lane = tid & 31;
    const int warp = tid >> 5;
    const int we = warp >> 3;            // edge half (0/1)
    const int wn = warp & 7;             // 16-col group
    const int g = lane >> 2, t = lane & 3;

    // B fragments of W2, loaded once (registers, 64 per thread)
    unsigned bfr[2][16][2];
#pragma unroll
    for (int j = 0; j < 2; ++j) {
        const int ncol = wn * 16 + j * 8 + g;
#pragma unroll
        for (int kk = 0; kk < 16; ++kk) {
            bfr[j][kk][0] = f2tf(__ldg(W2 + (size_t)(kk * 8 + t) * H + ncol));
            bfr[j][kk][1] = f2tf(__ldg(W2 + (size_t)(kk * 8 + t + 4) * H + ncol));
        }
    }
    // phase-1 constants (feature f = tid&127)
    const int f = tid & 127;
    const float w1cf = w1c[f];
    const float b1f = b1[f];
    const int fconst = ((f >> 3) * FR) + (f & 3) * 4 + 2 * ((f >> 2) & 1);
    // epilogue bias
    float b2v[2][2];
#pragma unroll
    for (int j = 0; j < 2; ++j) {
        b2v[j][0] = b2[wn * 16 + j * 8 + t * 2];
        b2v[j][1] = b2[wn * 16 + j * 8 + t * 2 + 1];
    }

    const int ntiles = (Etot + TE - 1) / TE;
    for (int tile = blockIdx.x; tile < ntiles; tile += gridDim.x) {
        const int e0 = tile * TE;
        const int cnt = min(TE, Etot - e0);

        // ---- meta + coord update ----
        if (tid < TE) {
            int e = e0 + tid;
            int s = 0, dd = 0; float dist = 0.f;
            if (tid < cnt) {
                float rx, ry, rz;
                if (e < E) { s = ei[e]; dd = ei[E + e]; }
                else       { s = e - E; dd = s; }
                rx = pos[s * 3 + 0] - pos[dd * 3 + 0];
                ry = pos[s * 3 + 1] - pos[dd * 3 + 1];
                rz = pos[s * 3 + 2] - pos[dd * 3 + 2];
                dist = sqrtf(rx * rx + ry * ry + rz * rz);
                float inv = wnode[s] / (dist + EPS);
                atomicAdd(dpos + dd * 3 + 0, rx * inv);
                atomicAdd(dpos + dd * 3 + 1, ry * inv);
                atomicAdd(dpos + dd * 3 + 2, rz * inv);
            }
            ssrc[tid] = s; sdst[tid] = dd; sdist[tid] = dist;
        }
        __syncthreads();

        // ---- phase 1: u, frag-packed with tf32 cvt ----
        {
            const int qb = (tid >> 7) * 32;  // edge quarter
            const float* Af = A + f;
            const float* Bf = B + f;
#pragma unroll 4
            for (int i = 0; i < 32; ++i) {
                int e = qb + i;
                int s = ssrc[e], dd = sdst[e];
                float pre = __ldg(Af + (size_t)dd * H) + __ldg(Bf + (size_t)s * H)
                          + sdist[e] * w1cf + b1f;
                int addr = (e >> 4) * (16 * FR) + (e & 7) * 16 + ((e >> 3) & 1) + fconst;
                U[addr] = __uint_as_float(f2tf(silu_f(pre)));
            }
        }
        __syncthreads();

        // ---- phase 2: tf32 mma + epilogue scatter ----
#pragma unroll
        for (int i = 0; i < 4; ++i) {
            const int mt = we * 4 + i;
            float c[2][4];
#pragma unroll
            for (int j = 0; j < 2; ++j)
#pragma unroll
                for (int s = 0; s < 4; ++s) c[j][s] = 0.0f;

            const float* ub = U + mt * (16 * FR) + lane * 4;
#pragma unroll
            for (int kk = 0; kk < 16; ++kk) {
                float4 av = *(const float4*)(ub + kk * FR);
                unsigned a[4] = {__float_as_uint(av.x), __float_as_uint(av.y),
                                 __float_as_uint(av.z), __float_as_uint(av.w)};
                mma_tf32(c[0], a, bfr[0][kk]);
                mma_tf32(c[1], a, bfr[1][kk]);
            }
            // epilogue: silu + v2 scatter-add
            const int e_lo = mt * 16 + g;
            const int e_hi = e_lo + 8;
#pragma unroll
            for (int j = 0; j < 2; ++j) {
                const int col = wn * 16 + j * 8 + t * 2;
                if (e_lo < cnt) {
                    int dd = sdst[e_lo];
                    red_add_v2(agg + (size_t)dd * H + col,
                               silu_f(c[j][0] + b2v[j][0]),
                               silu_f(c[j][1] + b2v[j][1]));
                }
                if (e_hi < cnt) {
                    int dd = sdst[e_hi];
                    red_add_v2(agg + (size_t)dd * H + col,
                               silu_f(c[j][2] + b2v[j][0]),
                               silu_f(c[j][3] + b2v[j][1]));
                }
            }
        }
        __syncthreads();
    }
}

// ---------------- small utility kernels --------------------------------------
__global__ void copy_kernel(float* __restrict__ dst, const float* __restrict__ src, int n) {
    int i = blockIdx.x * blockDim.x + threadIdx.x;
    if (i < n) dst[i] = src[i];
}
__global__ void add_kernel(float* __restrict__ dst, const float* __restrict__ src, int n) {
    int i = blockIdx.x * blockDim.x + threadIdx.x;
    if (i < n) dst[i] += src[i];
}
__global__ void zero2_kernel(float* __restrict__ a, int n1, float* __restrict__ b, int n2) {
    int i = blockIdx.x * blockDim.x + threadIdx.x;
    if (i < n1) a[i] = 0.0f;
    else if (i - n1 < n2) b[i - n1] = 0.0f;
}

// ---------------- host orchestration -----------------------------------------
extern "C" void kernel_launch(void* const* d_in, const int* in_sizes, int n_in,
                              void* d_out, int out_size)
{
    const float* h_in   = (const float*)d_in[0];
    const float* pos_in = (const float*)d_in[1];
    const int*   ei     = (const int*)d_in[2];
    const float* embW   = (const float*)d_in[3];
    const float* embB   = (const float*)d_in[4];
    const float* msgW1  = (const float*)d_in[5];
    const float* msgB1  = (const float*)d_in[6];
    const float* msgW2  = (const float*)d_in[7];
    const float* msgB2  = (const float*)d_in[8];
    const float* cW1    = (const float*)d_in[9];
    const float* cB1    = (const float*)d_in[10];
    const float* cW2    = (const float*)d_in[11];
    const float* cB2    = (const float*)d_in[12];
    const float* nW1    = (const float*)d_in[13];
    const float* nB1    = (const float*)d_in[14];
    const float* nW2    = (const float*)d_in[15];
    const float* nB2    = (const float*)d_in[16];
    const float* oW1    = (const float*)d_in[17];
    const float* oB1    = (const float*)d_in[18];
    const float* oW2    = (const float*)d_in[19];
    const float* oB2    = (const float*)d_in[20];

    const int N = in_sizes[1] / 3;
    const int E = in_sizes[2] / 2;
    const int Etot = E + N;
    const int INDIM = in_sizes[0] / N;

    float *bh, *bA, *bB, *bC1, *bagg, *bT, *bpos, *bdpos, *bwn;
    cudaGetSymbolAddress((void**)&bh, g_h);
    cudaGetSymbolAddress((void**)&bA, g_A);
    cudaGetSymbolAddress((void**)&bB, g_B);
    cudaGetSymbolAddress((void**)&bC1, g_C1);
    cudaGetSymbolAddress((void**)&bagg, g_agg);
    cudaGetSymbolAddress((void**)&bT, g_T);
    cudaGetSymbolAddress((void**)&bpos, g_pos);
    cudaGetSymbolAddress((void**)&bdpos, g_dpos);
    cudaGetSymbolAddress((void**)&bwn, g_wnode);

    const int NODE_SMEM = 128 * FR * 4;                     // 69632 B
    const int EDGE_SMEM = 128 * FR * 4 + TE * 4 + 2 * TE * 4;
    cudaFuncSetAttribute(node_gemm,
                         cudaFuncAttributeMaxDynamicSharedMemorySize, NODE_SMEM);
    cudaFuncSetAttribute(fused3_gemm,
                         cudaFuncAttributeMaxDynamicSharedMemorySize, NODE_SMEM);
    cudaFuncSetAttribute(edge_kernel,
                         cudaFuncAttributeMaxDynamicSharedMemorySize, EDGE_SMEM);

    const int gn = (N + 127) / 128;
    const int t256p = (N * 3 + 255) / 256;
    const int nz = N * H + N * 3;

    // h = h_in @ emb_W + emb_b
    node_gemm<<<gn, 512, NODE_SMEM>>>(h_in, INDIM, nullptr, 0, embW, embB,
                                      nullptr, 0, bh, N);
    copy_kernel<<<t256p, 256>>>(bpos, pos_in, N * 3);

    for (int l = 0; l < LAYERS; ++l) {
        const float* W1a = msgW1 + (size_t)l * 257 * H;
        const float* W1b = W1a + 128 * H;
        const float* W1c = msgW1 + (size_t)l * 257 * H + 256 * H;

        fused3_gemm<<<dim3(gn, 3), 512, NODE_SMEM>>>(
            bh, cW1 + (size_t)l * H * H, cB1 + l * H, W1a, W1b, bC1, bA, bB, N);
        wnode_kernel<<<(N * 32 + 255) / 256, 256>>>(bC1, cW2 + (size_t)l * H,
                                                    cB2 + l, bwn, N);
        zero2_kernel<<<(nz + 255) / 256, 256>>>(bagg, N * H, bdpos, N * 3);

        edge_kernel<<<148, 512, EDGE_SMEM>>>(
            ei, E, Etot, bA, bB, bpos, bwn,
            msgW2 + (size_t)l * H * H, msgB1 + l * H, msgB2 + l * H, W1c,
            bagg, bdpos);

        node_gemm<<<gn, 512, NODE_SMEM>>>(bh, H, bagg, H, nW1 + (size_t)l * 2 * H * H,
                                          nB1 + l * H, nullptr, 1, bT, N);
        node_gemm<<<gn, 512, NODE_SMEM>>>(bT, H, nullptr, 0, nW2 + (size_t)l * H * H,
                                          nB2 + l * H, bh, 0, bh, N);
        add_kernel<<<t256p, 256>>>(bpos, bdpos, N * 3);
    }

    node_gemm<<<gn, 512, NODE_SMEM>>>(bh, H, nullptr, 0, oW1, oB1, nullptr, 1, bT, N);
    node_gemm<<<gn, 512, NODE_SMEM>>>(bT, H, nullptr, 0, oW2, oB2, nullptr, 0,
                                      (float*)d_out, N);

    if (out_size >= N * H + N * 3) {
        copy_kernel<<<t256p, 256>>>((float*)d_out + (size_t)N * H, bpos, N * 3);
    }
}

// round 5
// speedup vs baseline: 2.1314x; 1.0148x over previous
#include <cuda_runtime.h>
#include <math.h>

#define H 128
#define LAYERS 4
#define NMAX 50176
#define EPS 1e-8f
#define FR 136   // fragment-pack stride in floats (128 + 8 pad)

// ---------------- static device scratch (allocation-free rule) ----------------
__device__ float g_h[NMAX * H];
__device__ float g_A[NMAX * H];     // (h @ msgW1[0:128])   -> indexed by dst
__device__ float g_B[NMAX * H];     // (h @ msgW1[128:256]) -> indexed by src
__device__ float g_agg[NMAX * H];   // message scatter target
__device__ float g_T[NMAX * H];     // generic temp
__device__ float g_pos[NMAX * 3];
__device__ float g_dpos[NMAX * 3];
__device__ float g_wnode[NMAX];

__device__ __forceinline__ float silu_f(float x) {
    return x / (1.0f + __expf(-x));
}

__device__ __forceinline__ unsigned f2tf(float x) {
    unsigned r;
    asm("cvt.rna.tf32.f32 %0, %1;" : "=r"(r) : "f"(x));
    return r;
}

__device__ __forceinline__ void mma_tf32(float c[4], const unsigned a[4], const unsigned b[2]) {
    asm volatile(
        "mma.sync.aligned.m16n8k8.row.col.f32.tf32.tf32.f32 "
        "{%0,%1,%2,%3}, {%4,%5,%6,%7}, {%8,%9}, {%0,%1,%2,%3};"
        : "+f"(c[0]), "+f"(c[1]), "+f"(c[2]), "+f"(c[3])
        : "r"(a[0]), "r"(a[1]), "r"(a[2]), "r"(a[3]), "r"(b[0]), "r"(b[1]));
}

__device__ __forceinline__ void red_add_v4(float* addr, float a, float b, float c, float d) {
    asm volatile("red.global.add.v4.f32 [%0], {%1,%2,%3,%4};"
                 :: "l"(addr), "f"(a), "f"(b), "f"(c), "f"(d) : "memory");
}

// fragment-packed smem address for element (row r in 0..127, k in 0..127)
__device__ __forceinline__ int fp_addr(int r, int k) {
    return ((r >> 4) * 16 + (k >> 3)) * FR + ((r & 7) * 4 + (k & 3)) * 4
         + ((r >> 3) & 1) + 2 * ((k >> 2) & 1);
}

// ---------------- node-side GEMM (tf32 mma), 512 threads ----------------------
template <int KS>   // k-steps in this chunk (8 or 16)
__device__ __forceinline__ void node_chunk(
    const float* __restrict__ src, int stride, int coff, int kc,
    const float* __restrict__ W,
    float (&d)[4][2][4], float* Xs, int n, int row0)
{
    const int tid = threadIdx.x;
    const int lane = tid & 31;
    const int warp = tid >> 5;
    const int we = warp >> 3;
    const int wn = warp & 7;
    const int g = lane >> 2, t = lane & 3;

    __syncthreads();
    constexpr int Q4 = KS * 2;
#pragma unroll
    for (int q = tid; q < 128 * Q4; q += 512) {
        int r = q / Q4;
        int kq = (q - r * Q4) << 2;
        int row = row0 + r;
        float4 v = make_float4(0.f, 0.f, 0.f, 0.f);
        if (row < n) v = *(const float4*)(src + (size_t)row * stride + coff + kq);
        float vv[4] = {v.x, v.y, v.z, v.w};
#pragma unroll
        for (int s2 = 0; s2 < 4; ++s2)
            Xs[fp_addr(r, kq + s2)] = __uint_as_float(f2tf(vv[s2]));
    }
    unsigned bfr[2][KS][2];
#pragma unroll
    for (int j = 0; j < 2; ++j) {
        const int ncol = wn * 16 + j * 8 + g;
#pragma unroll
        for (int kk = 0; kk < KS; ++kk) {
            bfr[j][kk][0] = f2tf(__ldg(W + (size_t)(kc + kk * 8 + t) * H + ncol));
            bfr[j][kk][1] = f2tf(__ldg(W + (size_t)(kc + kk * 8 + t + 4) * H + ncol));
        }
    }
    __syncthreads();

#pragma unroll
    for (int i = 0; i < 4; ++i) {
        const float* ub = Xs + ((we * 4 + i) * 16) * FR + lane * 4;
#pragma unroll
        for (int kk = 0; kk < KS; ++kk) {
            float4 av = *(const float4*)(ub + kk * FR);
            unsigned a[4] = {__float_as_uint(av.x), __float_as_uint(av.y),
                             __float_as_uint(av.z), __float_as_uint(av.w)};
            mma_tf32(d[i][0], a, bfr[0][kk]);
            mma_tf32(d[i][1], a, bfr[1][kk]);
        }
    }
}

// act: 0 = none, 1 = silu, 2 = silu + wnode-dot (no Y store)
__device__ __forceinline__ void gemm_body_mma(
    const float* __restrict__ X1, int K1,
    const float* __restrict__ X2, int K2,
    const float* __restrict__ W,
    const float* __restrict__ bias,
    const float* __restrict__ res,
    int act,
    float* __restrict__ Y, int n, int row0, float* Xs,
    const float* __restrict__ w2vec, float* __restrict__ wnout)
{
    const int tid = threadIdx.x;
    const int lane = tid & 31;
    const int warp = tid >> 5;
    const int we = warp >> 3;
    const int wn = warp & 7;
    const int g = lane >> 2, t = lane & 3;

    float d[4][2][4];
#pragma unroll
    for (int i = 0; i < 4; ++i)
#pragma unroll
        for (int j = 0; j < 2; ++j)
#pragma unroll
            for (int s = 0; s < 4; ++s) d[i][j][s] = 0.0f;

    const int Ktot = K1 + K2;
    for (int kc = 0; kc < Ktot; kc += 128) {
        const int kchunk = min(128, Ktot - kc);
        const float* src; int stride, coff;
        if (kc < K1) { src = X1; stride = K1; coff = kc; }
        else         { src = X2; stride = K2; coff = kc - K1; }
        if (kchunk == 128) node_chunk<16>(src, stride, coff, kc, W, d, Xs, n, row0);
        else               node_chunk<8>(src, stride, coff, kc, W, d, Xs, n, row0);
    }

    if (act == 2) {
        // silu + dot with w2vec, quad-reduce, atomic into wnout. No Y store.
        float b0[2], b1[2], w20[2], w21[2];
#pragma unroll
        for (int j = 0; j < 2; ++j) {
            const int col = wn * 16 + j * 8 + t * 2;
            b0[j] = bias ? bias[col] : 0.0f;
            b1[j] = bias ? bias[col + 1] : 0.0f;
            w20[j] = w2vec[col];
            w21[j] = w2vec[col + 1];
        }
#pragma unroll
        for (int i = 0; i < 4; ++i) {
#pragma unroll
            for (int half = 0; half < 2; ++half) {
                int row = row0 + (we * 4 + i) * 16 + g + half * 8;
                float s = 0.0f;
#pragma unroll
                for (int j = 0; j < 2; ++j) {
                    float o0 = silu_f(d[i][j][half * 2 + 0] + b0[j]);
                    float o1 = silu_f(d[i][j][half * 2 + 1] + b1[j]);
                    s = fmaf(o0, w20[j], fmaf(o1, w21[j], s));
                }
                s += __shfl_xor_sync(0xffffffffu, s, 1);
                s += __shfl_xor_sync(0xffffffffu, s, 2);
                if (t == 0 && row < n) atomicAdd(wnout + row, s);
            }
        }
        return;
    }

    // standard epilogue: 2-wide stores, bias/silu/residual
#pragma unroll
    for (int j = 0; j < 2; ++j) {
        const int col = wn * 16 + j * 8 + t * 2;
        float b0 = bias ? bias[col] : 0.0f;
        float b1v = bias ? bias[col + 1] : 0.0f;
#pragma unroll
        for (int i = 0; i < 4; ++i) {
            int rb = row0 + (we * 4 + i) * 16 + g;
#pragma unroll
            for (int half = 0; half < 2; ++half) {
                int row = rb + half * 8;
                if (row < n) {
                    float o0 = d[i][j][half * 2 + 0] + b0;
                    float o1 = d[i][j][half * 2 + 1] + b1v;
                    if (act == 1) { o0 = silu_f(o0); o1 = silu_f(o1); }
                    if (res) {
                        o0 += res[(size_t)row * H + col];
                        o1 += res[(size_t)row * H + col + 1];
                    }
                    *(float2*)(Y + (size_t)row * H + col) = make_float2(o0, o1);
                }
            }
        }
    }
}

__global__ __launch_bounds__(512) void node_gemm(
    const float* __restrict__ X1, int K1,
    const float* __restrict__ X2, int K2,
    const float* __restrict__ W,
    const float* __restrict__ bias,
    const float* __restrict__ res,
    int act,
    float* __restrict__ Y, int n)
{
    extern __shared__ float Xs[];
    gemm_body_mma(X1, K1, X2, K2, W, bias, res, act, Y, n, blockIdx.x * 128, Xs,
                  nullptr, nullptr);
}

// one launch: wnode (via cW1/cW2 dot, atomic), A = h@W1a, B = h@W1b
__global__ __launch_bounds__(512) void fused3_gemm(
    const float* __restrict__ hbuf,
    const float* __restrict__ cW1, const float* __restrict__ cB1,
    const float* __restrict__ cW2, float* __restrict__ wn,
    const float* __restrict__ W1a, const float* __restrict__ W1b,
    float* __restrict__ A, float* __restrict__ B, int n)
{
    extern __shared__ float Xs[];
    if (blockIdx.y == 0) {
        gemm_body_mma(hbuf, H, nullptr, 0, cW1, cB1, nullptr, 2, nullptr, n,
                      blockIdx.x * 128, Xs, cW2, wn);
    } else if (blockIdx.y == 1) {
        gemm_body_mma(hbuf, H, nullptr, 0, W1a, nullptr, nullptr, 0, A, n,
                      blockIdx.x * 128, Xs, nullptr, nullptr);
    } else {
        gemm_body_mma(hbuf, H, nullptr, 0, W1b, nullptr, nullptr, 0, B, n,
                      blockIdx.x * 128, Xs, nullptr, nullptr);
    }
}

// ---------------- fused edge kernel (tf32 mma, 512 threads) -------------------
#define TE 128
__global__ __launch_bounds__(512) void edge_kernel(
    const int* __restrict__ ei, int E, int Etot,
    const float* __restrict__ A, const float* __restrict__ B,
    const float* __restrict__ pos, const float* __restrict__ wnode,
    const float* __restrict__ W2, const float* __restrict__ b1,
    const float* __restrict__ b2, const float* __restrict__ w1c,
    float* __restrict__ agg, float* __restrict__ dpos)
{
    extern __shared__ float smbuf[];
    float* U = smbuf;                    // 128 frags * FR floats
    float* sdist = U + 128 * FR;         // 128
    int* ssrc = (int*)(sdist + TE);      // 128
    int* sdst = ssrc + TE;               // 128

    const int tid = threadIdx.x;
    const int lane = tid & 31;
    const int warp = tid >> 5;
    const int we = warp >> 3;            // edge half (0/1)
    const int wn = warp & 7;             // 16-col group
    const int g = lane >> 2, t = lane & 3;

    // B fragments of W2, loaded once
    unsigned bfr[2][16][2];
#pragma unroll
    for (int j = 0; j < 2; ++j) {
        const int ncol = wn * 16 + j * 8 + g;
#pragma unroll
        for (int kk = 0; kk < 16; ++kk) {
            bfr[j][kk][0] = f2tf(__ldg(W2 + (size_t)(kk * 8 + t) * H + ncol));
            bfr[j][kk][1] = f2tf(__ldg(W2 + (size_t)(kk * 8 + t + 4) * H + ncol));
        }
    }
    const int f = tid & 127;
    const float w1cf = w1c[f];
    const float b1f = b1[f];
    const int fconst = ((f >> 3) * FR) + (f & 3) * 4 + 2 * ((f >> 2) & 1);
    float b2v[2][2];
#pragma unroll
    for (int j = 0; j < 2; ++j) {
        b2v[j][0] = b2[wn * 16 + j * 8 + t * 2];
        b2v[j][1] = b2[wn * 16 + j * 8 + t * 2 + 1];
    }

    const int ntiles = (Etot + TE - 1) / TE;
    for (int tile = blockIdx.x; tile < ntiles; tile += gridDim.x) {
        const int e0 = tile * TE;
        const int cnt = min(TE, Etot - e0);

        // ---- meta + coord update ----
        if (tid < TE) {
            int e = e0 + tid;
            int s = 0, dd = 0; float dist = 0.f;
            if (tid < cnt) {
                float rx, ry, rz;
                if (e < E) { s = ei[e]; dd = ei[E + e]; }
                else       { s = e - E; dd = s; }
                rx = pos[s * 3 + 0] - pos[dd * 3 + 0];
                ry = pos[s * 3 + 1] - pos[dd * 3 + 1];
                rz = pos[s * 3 + 2] - pos[dd * 3 + 2];
                dist = sqrtf(rx * rx + ry * ry + rz * rz);
                float inv = wnode[s] / (dist + EPS);
                atomicAdd(dpos + dd * 3 + 0, rx * inv);
                atomicAdd(dpos + dd * 3 + 1, ry * inv);
                atomicAdd(dpos + dd * 3 + 2, rz * inv);
            }
            ssrc[tid] = s; sdst[tid] = dd; sdist[tid] = dist;
        }
        __syncthreads();

        // ---- phase 1: u, frag-packed with tf32 cvt ----
        {
            const int qb = (tid >> 7) * 32;
            const float* Af = A + f;
            const float* Bf = B + f;
#pragma unroll 4
            for (int i = 0; i < 32; ++i) {
                int e = qb + i;
                int s = ssrc[e], dd = sdst[e];
                float pre = __ldg(Af + (size_t)dd * H) + __ldg(Bf + (size_t)s * H)
                          + sdist[e] * w1cf + b1f;
                int addr = (e >> 4) * (16 * FR) + (e & 7) * 16 + ((e >> 3) & 1) + fconst;
                U[addr] = __uint_as_float(f2tf(silu_f(pre)));
            }
        }
        __syncthreads();

        // ---- phase 2: tf32 mma + shuffle-paired v4 scatter ----
#pragma unroll
        for (int i = 0; i < 4; ++i) {
            const int mt = we * 4 + i;
            float c[2][4];
#pragma unroll
            for (int j = 0; j < 2; ++j)
#pragma unroll
                for (int s = 0; s < 4; ++s) c[j][s] = 0.0f;

            const float* ub = U + mt * (16 * FR) + lane * 4;
#pragma unroll
            for (int kk = 0; kk < 16; ++kk) {
                float4 av = *(const float4*)(ub + kk * FR);
                unsigned a[4] = {__float_as_uint(av.x), __float_as_uint(av.y),
                                 __float_as_uint(av.z), __float_as_uint(av.w)};
                mma_tf32(c[0], a, bfr[0][kk]);
                mma_tf32(c[1], a, bfr[1][kk]);
            }

            const int e_lo = mt * 16 + g;
            const int e_hi = e_lo + 8;
#pragma unroll
            for (int j = 0; j < 2; ++j) {
                float v0 = silu_f(c[j][0] + b2v[j][0]);
                float v1 = silu_f(c[j][1] + b2v[j][1]);
                float v2 = silu_f(c[j][2] + b2v[j][0]);
                float v3 = silu_f(c[j][3] + b2v[j][1]);
                // partner lane (t^1) holds the adjacent 2 columns of the same rows
                float w0 = __shfl_xor_sync(0xffffffffu, v0, 1);
                float w1 = __shfl_xor_sync(0xffffffffu, v1, 1);
                float w2 = __shfl_xor_sync(0xffffffffu, v2, 1);
                float w3 = __shfl_xor_sync(0xffffffffu, v3, 1);
                if ((t & 1) == 0) {
                    const int col4 = wn * 16 + j * 8 + t * 2;  // t in {0,2} -> 16B aligned
                    if (e_lo < cnt)
                        red_add_v4(agg + (size_t)sdst[e_lo] * H + col4, v0, v1, w0, w1);
                    if (e_hi < cnt)
                        red_add_v4(agg + (size_t)sdst[e_hi] * H + col4, v2, v3, w2, w3);
                }
            }
        }
        __syncthreads();
    }
}

// ---------------- small utility kernels --------------------------------------
__global__ void copy_kernel(float* __restrict__ dst, const float* __restrict__ src, int n) {
    int i = blockIdx.x * blockDim.x + threadIdx.x;
    if (i < n) dst[i] = src[i];
}
__global__ void add_kernel(float* __restrict__ dst, const float* __restrict__ src, int n) {
    int i = blockIdx.x * blockDim.x + threadIdx.x;
    if (i < n) dst[i] += src[i];
}
// zero agg + dpos, init wnode to cb2[0]
__global__ void zero3_kernel(float* __restrict__ a, int n1, float* __restrict__ b, int n2,
                             float* __restrict__ w, int n3, const float* __restrict__ cb2) {
    int i = blockIdx.x * blockDim.x + threadIdx.x;
    if (i < n1) a[i] = 0.0f;
    else if (i - n1 < n2) b[i - n1] = 0.0f;
    else if (i - n1 - n2 < n3) w[i - n1 - n2] = cb2[0];
}

// ---------------- host orchestration -----------------------------------------
extern "C" void kernel_launch(void* const* d_in, const int* in_sizes, int n_in,
                              void* d_out, int out_size)
{
    const float* h_in   = (const float*)d_in[0];
    const float* pos_in = (const float*)d_in[1];
    const int*   ei     = (const int*)d_in[2];
    const float* embW   = (const float*)d_in[3];
    const float* embB   = (const float*)d_in[4];
    const float* msgW1  = (const float*)d_in[5];
    const float* msgB1  = (const float*)d_in[6];
    const float* msgW2  = (const float*)d_in[7];
    const float* msgB2  = (const float*)d_in[8];
    const float* cW1    = (const float*)d_in[9];
    const float* cB1    = (const float*)d_in[10];
    const float* cW2    = (const float*)d_in[11];
    const float* cB2    = (const float*)d_in[12];
    const float* nW1    = (const float*)d_in[13];
    const float* nB1    = (const float*)d_in[14];
    const float* nW2    = (const float*)d_in[15];
    const float* nB2    = (const float*)d_in[16];
    const float* oW1    = (const float*)d_in[17];
    const float* oB1    = (const float*)d_in[18];
    const float* oW2    = (const float*)d_in[19];
    const float* oB2    = (const float*)d_in[20];

    const int N = in_sizes[1] / 3;
    const int E = in_sizes[2] / 2;
    const int Etot = E + N;
    const int INDIM = in_sizes[0] / N;

    float *bh, *bA, *bB, *bagg, *bT, *bpos, *bdpos, *bwn;
    cudaGetSymbolAddress((void**)&bh, g_h);
    cudaGetSymbolAddress((void**)&bA, g_A);
    cudaGetSymbolAddress((void**)&bB, g_B);
    cudaGetSymbolAddress((void**)&bagg, g_agg);
    cudaGetSymbolAddress((void**)&bT, g_T);
    cudaGetSymbolAddress((void**)&bpos, g_pos);
    cudaGetSymbolAddress((void**)&bdpos, g_dpos);
    cudaGetSymbolAddress((void**)&bwn, g_wnode);

    const int NODE_SMEM = 128 * FR * 4;
    const int EDGE_SMEM = 128 * FR * 4 + TE * 4 + 2 * TE * 4;
    cudaFuncSetAttribute(node_gemm,
                         cudaFuncAttributeMaxDynamicSharedMemorySize, NODE_SMEM);
    cudaFuncSetAttribute(fused3_gemm,
                         cudaFuncAttributeMaxDynamicSharedMemorySize, NODE_SMEM);
    cudaFuncSetAttribute(edge_kernel,
                         cudaFuncAttributeMaxDynamicSharedMemorySize, EDGE_SMEM);

    const int gn = (N + 127) / 128;
    const int t256p = (N * 3 + 255) / 256;
    const int nz = N * H + N * 3 + N;

    node_gemm<<<gn, 512, NODE_SMEM>>>(h_in, INDIM, nullptr, 0, embW, embB,
                                      nullptr, 0, bh, N);
    copy_kernel<<<t256p, 256>>>(bpos, pos_in, N * 3);

    for (int l = 0; l < LAYERS; ++l) {
        const float* W1a = msgW1 + (size_t)l * 257 * H;
        const float* W1b = W1a + 128 * H;
        const float* W1c = msgW1 + (size_t)l * 257 * H + 256 * H;

        zero3_kernel<<<(nz + 255) / 256, 256>>>(bagg, N * H, bdpos, N * 3,
                                                bwn, N, cB2 + l);
        fused3_gemm<<<dim3(gn, 3), 512, NODE_SMEM>>>(
            bh, cW1 + (size_t)l * H * H, cB1 + l * H, cW2 + (size_t)l * H, bwn,
            W1a, W1b, bA, bB, N);

        edge_kernel<<<148, 512, EDGE_SMEM>>>(
            ei, E, Etot, bA, bB, bpos, bwn,
            msgW2 + (size_t)l * H * H, msgB1 + l * H, msgB2 + l * H, W1c,
            bagg, bdpos);

        node_gemm<<<gn, 512, NODE_SMEM>>>(bh, H, bagg, H, nW1 + (size_t)l * 2 * H * H,
                                          nB1 + l * H, nullptr, 1, bT, N);
        node_gemm<<<gn, 512, NODE_SMEM>>>(bT, H, nullptr, 0, nW2 + (size_t)l * H * H,
                                          nB2 + l * H, bh, 0, bh, N);
        add_kernel<<<t256p, 256>>>(bpos, bdpos, N * 3);
    }

    node_gemm<<<gn, 512, NODE_SMEM>>>(bh, H, nullptr, 0, oW1, oB1, nullptr, 1, bT, N);
    node_gemm<<<gn, 512, NODE_SMEM>>>(bT, H, nullptr, 0, oW2, oB2, nullptr, 0,
                                      (float*)d_out, N);

    if (out_size >= N * H + N * 3) {
        copy_kernel<<<t256p, 256>>>((float*)d_out + (size_t)N * H, bpos, N * 3);
    }
}

// round 6
// speedup vs baseline: 3.2559x; 1.5276x over previous
#include <cuda_runtime.h>
#include <math.h>

#define H 128
#define LAYERS 4
#define NMAX 50176
#define EPS 1e-8f
#define FR 136   // fragment-pack stride in floats (128 + 8 pad)

// ---------------- static device scratch (allocation-free rule) ----------------
__device__ float g_h[NMAX * H];
__device__ float g_A[NMAX * H];     // (h @ msgW1[0:128])   -> indexed by dst
__device__ float g_B[NMAX * H];     // (h @ msgW1[128:256]) -> indexed by src
__device__ float g_agg[NMAX * H];   // message scatter target
__device__ float g_T[NMAX * H];     // generic temp
__device__ float g_pos[NMAX * 3];
__device__ float g_dpos[NMAX * 3];
__device__ float g_wnode[NMAX];

__device__ __forceinline__ float silu_f(float x) {
    return x / (1.0f + __expf(-x));
}

__device__ __forceinline__ unsigned f2tf(float x) {
    unsigned r;
    asm("cvt.rna.tf32.f32 %0, %1;" : "=r"(r) : "f"(x));
    return r;
}

__device__ __forceinline__ void mma_tf32(float c[4], const unsigned a[4], const unsigned b[2]) {
    asm volatile(
        "mma.sync.aligned.m16n8k8.row.col.f32.tf32.tf32.f32 "
        "{%0,%1,%2,%3}, {%4,%5,%6,%7}, {%8,%9}, {%0,%1,%2,%3};"
        : "+f"(c[0]), "+f"(c[1]), "+f"(c[2]), "+f"(c[3])
        : "r"(a[0]), "r"(a[1]), "r"(a[2]), "r"(a[3]), "r"(b[0]), "r"(b[1]));
}

__device__ __forceinline__ void red_add_v4(float* addr, float a, float b, float c, float d) {
    asm volatile("red.global.add.v4.f32 [%0], {%1,%2,%3,%4};"
                 :: "l"(addr), "f"(a), "f"(b), "f"(c), "f"(d) : "memory");
}

// fragment-packed smem address for (row r in 0..63, k in 0..127)
__device__ __forceinline__ int fp_addr(int r, int k) {
    return ((r >> 4) * 16 + (k >> 3)) * FR + ((r & 7) * 4 + (k & 3)) * 4
         + ((r >> 3) & 1) + 2 * ((k >> 2) & 1);
}

// ---------------- node-side GEMM (tf32 mma), 64-row tiles, 256 threads --------
// B fragments reloaded from global (L1-resident) each k-step: no bfr registers.
template <int KS>   // k-steps in this chunk (8 or 16)
__device__ __forceinline__ void node_chunk64(
    const float* __restrict__ src, int stride, int coff, int kc,
    const float* __restrict__ W,
    float (&d)[4][2][4], float* Xs, int n, int row0)
{
    const int tid = threadIdx.x;
    const int lane = tid & 31;
    const int wn = tid >> 5;            // 8 warps = 8 col groups of 16
    const int g = lane >> 2, t = lane & 3;

    __syncthreads();
    constexpr int Q4 = KS * 2;          // float4 per row
#pragma unroll
    for (int q = tid; q < 64 * Q4; q += 256) {
        int r = q / Q4;
        int kq = (q - r * Q4) << 2;
        int row = row0 + r;
        float4 v = make_float4(0.f, 0.f, 0.f, 0.f);
        if (row < n) v = *(const float4*)(src + (size_t)row * stride + coff + kq);
        float vv[4] = {v.x, v.y, v.z, v.w};
#pragma unroll
        for (int s2 = 0; s2 < 4; ++s2)
            Xs[fp_addr(r, kq + s2)] = __uint_as_float(f2tf(vv[s2]));
    }
    __syncthreads();

    const int ncol0 = wn * 16 + g;
#pragma unroll
    for (int kk = 0; kk < KS; ++kk) {
        const float* wr = W + (size_t)(kc + kk * 8 + t) * H;
        unsigned bb0[2], bb1[2];
        bb0[0] = f2tf(__ldg(wr + ncol0));
        bb0[1] = f2tf(__ldg(wr + 4 * H + ncol0));
        bb1[0] = f2tf(__ldg(wr + ncol0 + 8));
        bb1[1] = f2tf(__ldg(wr + 4 * H + ncol0 + 8));
#pragma unroll
        for (int mt = 0; mt < 4; ++mt) {
            float4 av = *(const float4*)(Xs + (mt * 16 + kk) * FR + lane * 4);
            unsigned a[4] = {__float_as_uint(av.x), __float_as_uint(av.y),
                             __float_as_uint(av.z), __float_as_uint(av.w)};
            mma_tf32(d[mt][0], a, bb0);
            mma_tf32(d[mt][1], a, bb1);
        }
    }
}

// act: 0 = none, 1 = silu, 2 = silu + wnode-dot (no Y store)
__device__ __forceinline__ void gemm_body64(
    const float* __restrict__ X1, int K1,
    const float* __restrict__ X2, int K2,
    const float* __restrict__ W,
    const float* __restrict__ bias,
    const float* __restrict__ res,
    int act,
    float* __restrict__ Y, int n, int row0, float* Xs,
    const float* __restrict__ w2vec, float* __restrict__ wnout)
{
    const int tid = threadIdx.x;
    const int lane = tid & 31;
    const int wn = tid >> 5;
    const int g = lane >> 2, t = lane & 3;

    float d[4][2][4];
#pragma unroll
    for (int mt = 0; mt < 4; ++mt)
#pragma unroll
        for (int j = 0; j < 2; ++j)
#pragma unroll
            for (int s = 0; s < 4; ++s) d[mt][j][s] = 0.0f;

    const int Ktot = K1 + K2;
    for (int kc = 0; kc < Ktot; kc += 128) {
        const int kchunk = min(128, Ktot - kc);
        const float* src; int stride, coff;
        if (kc < K1) { src = X1; stride = K1; coff = kc; }
        else         { src = X2; stride = K2; coff = kc - K1; }
        if (kchunk == 128) node_chunk64<16>(src, stride, coff, kc, W, d, Xs, n, row0);
        else               node_chunk64<8>(src, stride, coff, kc, W, d, Xs, n, row0);
    }

    if (act == 2) {
        float b0[2], b1v[2], w20[2], w21[2];
#pragma unroll
        for (int j = 0; j < 2; ++j) {
            const int col = wn * 16 + j * 8 + t * 2;
            b0[j] = bias ? bias[col] : 0.0f;
            b1v[j] = bias ? bias[col + 1] : 0.0f;
            w20[j] = w2vec[col];
            w21[j] = w2vec[col + 1];
        }
#pragma unroll
        for (int mt = 0; mt < 4; ++mt) {
#pragma unroll
            for (int half = 0; half < 2; ++half) {
                int row = row0 + mt * 16 + g + half * 8;
                float s = 0.0f;
#pragma unroll
                for (int j = 0; j < 2; ++j) {
                    float o0 = silu_f(d[mt][j][half * 2 + 0] + b0[j]);
                    float o1 = silu_f(d[mt][j][half * 2 + 1] + b1v[j]);
                    s = fmaf(o0, w20[j], fmaf(o1, w21[j], s));
                }
                s += __shfl_xor_sync(0xffffffffu, s, 1);
                s += __shfl_xor_sync(0xffffffffu, s, 2);
                if (t == 0 && row < n) atomicAdd(wnout + row, s);
            }
        }
        return;
    }

#pragma unroll
    for (int j = 0; j < 2; ++j) {
        const int col = wn * 16 + j * 8 + t * 2;
        float b0 = bias ? bias[col] : 0.0f;
        float b1v = bias ? bias[col + 1] : 0.0f;
#pragma unroll
        for (int mt = 0; mt < 4; ++mt) {
#pragma unroll
            for (int half = 0; half < 2; ++half) {
                int row = row0 + mt * 16 + g + half * 8;
                if (row < n) {
                    float o0 = d[mt][j][half * 2 + 0] + b0;
                    float o1 = d[mt][j][half * 2 + 1] + b1v;
                    if (act == 1) { o0 = silu_f(o0); o1 = silu_f(o1); }
                    if (res) {
                        o0 += res[(size_t)row * H + col];
                        o1 += res[(size_t)row * H + col + 1];
                    }
                    *(float2*)(Y + (size_t)row * H + col) = make_float2(o0, o1);
                }
            }
        }
    }
}

__global__ __launch_bounds__(256, 3) void node_gemm(
    const float* __restrict__ X1, int K1,
    const float* __restrict__ X2, int K2,
    const float* __restrict__ W,
    const float* __restrict__ bias,
    const float* __restrict__ res,
    int act,
    float* __restrict__ Y, int n)
{
    extern __shared__ float Xs[];
    gemm_body64(X1, K1, X2, K2, W, bias, res, act, Y, n, blockIdx.x * 64, Xs,
                nullptr, nullptr);
}

// one launch: wnode (via cW1/cW2 dot, atomic), A = h@W1a, B = h@W1b
__global__ __launch_bounds__(256, 3) void fused3_gemm(
    const float* __restrict__ hbuf,
    const float* __restrict__ cW1, const float* __restrict__ cB1,
    const float* __restrict__ cW2, float* __restrict__ wn,
    const float* __restrict__ W1a, const float* __restrict__ W1b,
    float* __restrict__ A, float* __restrict__ B, int n)
{
    extern __shared__ float Xs[];
    if (blockIdx.y == 0) {
        gemm_body64(hbuf, H, nullptr, 0, cW1, cB1, nullptr, 2, nullptr, n,
                    blockIdx.x * 64, Xs, cW2, wn);
    } else if (blockIdx.y == 1) {
        gemm_body64(hbuf, H, nullptr, 0, W1a, nullptr, nullptr, 0, A, n,
                    blockIdx.x * 64, Xs, nullptr, nullptr);
    } else {
        gemm_body64(hbuf, H, nullptr, 0, W1b, nullptr, nullptr, 0, B, n,
                    blockIdx.x * 64, Xs, nullptr, nullptr);
    }
}

// ---------------- fused edge kernel (tf32 mma, 64-edge tiles, 256 threads) ----
#define TE 64
__global__ __launch_bounds__(256, 3) void edge_kernel(
    const int* __restrict__ ei, int E, int Etot,
    const float* __restrict__ A, const float* __restrict__ B,
    const float* __restrict__ pos, const float* __restrict__ wnode,
    const float* __restrict__ W2, const float* __restrict__ b1,
    const float* __restrict__ b2, const float* __restrict__ w1c,
    float* __restrict__ agg, float* __restrict__ dpos)
{
    extern __shared__ float smbuf[];
    float* U = smbuf;                    // 64 frags * FR floats (4 mt x 16 kk)
    float* sdist = U + 64 * FR;          // 64
    int* ssrc = (int*)(sdist + TE);      // 64
    int* sdst = ssrc + TE;               // 64

    const int tid = threadIdx.x;
    const int lane = tid & 31;
    const int wn = tid >> 5;             // 8 warps = 8 col groups of 16
    const int g = lane >> 2, t = lane & 3;

    // phase-1 constants: thread covers features fq*4 .. fq*4+3
    const int fq = lane;                 // 0..31 within warp
    const int eg = wn;                   // 8 edge groups of 8
    const float4 w1c4 = *(const float4*)(w1c + fq * 4);
    const float4 b1_4 = *(const float4*)(b1 + fq * 4);
    const int fragk = fq >> 1;
    const int slot2 = 2 * (fq & 1);
    // epilogue bias
    float b2v[2][2];
#pragma unroll
    for (int j = 0; j < 2; ++j) {
        b2v[j][0] = b2[wn * 16 + j * 8 + t * 2];
        b2v[j][1] = b2[wn * 16 + j * 8 + t * 2 + 1];
    }
    const int ncol0 = wn * 16 + g;

    const int ntiles = (Etot + TE - 1) / TE;
    for (int tile = blockIdx.x; tile < ntiles; tile += gridDim.x) {
        const int e0 = tile * TE;
        const int cnt = min(TE, Etot - e0);

        // ---- meta + coord update ----
        if (tid < TE) {
            int e = e0 + tid;
            int s = 0, dd = 0; float dist = 0.f;
            if (tid < cnt) {
                float rx, ry, rz;
                if (e < E) { s = ei[e]; dd = ei[E + e]; }
                else       { s = e - E; dd = s; }
                rx = pos[s * 3 + 0] - pos[dd * 3 + 0];
                ry = pos[s * 3 + 1] - pos[dd * 3 + 1];
                rz = pos[s * 3 + 2] - pos[dd * 3 + 2];
                dist = sqrtf(rx * rx + ry * ry + rz * rz);
                float inv = wnode[s] / (dist + EPS);
                atomicAdd(dpos + dd * 3 + 0, rx * inv);
                atomicAdd(dpos + dd * 3 + 1, ry * inv);
                atomicAdd(dpos + dd * 3 + 2, rz * inv);
            }
            ssrc[tid] = s; sdst[tid] = dd; sdist[tid] = dist;
        }
        __syncthreads();

        // ---- phase 1: u via LDG.128 gathers (4 features x 8 edges / thread) --
#pragma unroll
        for (int i = 0; i < 8; ++i) {
            int e = eg * 8 + i;
            int s = ssrc[e], dd = sdst[e];
            float dist = sdist[e];
            float4 a4 = *(const float4*)(A + (size_t)dd * H + fq * 4);
            float4 c4 = *(const float4*)(B + (size_t)s * H + fq * 4);
            int base0 = ((e >> 4) * 16 + fragk) * FR + (e & 7) * 16
                      + ((e >> 3) & 1) + slot2;
            U[base0 + 0]  = __uint_as_float(f2tf(silu_f(a4.x + c4.x + dist * w1c4.x + b1_4.x)));
            U[base0 + 4]  = __uint_as_float(f2tf(silu_f(a4.y + c4.y + dist * w1c4.y + b1_4.y)));
            U[base0 + 8]  = __uint_as_float(f2tf(silu_f(a4.z + c4.z + dist * w1c4.z + b1_4.z)));
            U[base0 + 12] = __uint_as_float(f2tf(silu_f(a4.w + c4.w + dist * w1c4.w + b1_4.w)));
        }
        __syncthreads();

        // ---- phase 2: tf32 mma, B frags from L1 ----
        float acc[4][2][4];
#pragma unroll
        for (int mt = 0; mt < 4; ++mt)
#pragma unroll
            for (int j = 0; j < 2; ++j)
#pragma unroll
                for (int s = 0; s < 4; ++s) acc[mt][j][s] = 0.0f;

#pragma unroll
        for (int kk = 0; kk < 16; ++kk) {
            const float* wr = W2 + (size_t)(kk * 8 + t) * H;
            unsigned bb0[2], bb1[2];
            bb0[0] = f2tf(__ldg(wr + ncol0));
            bb0[1] = f2tf(__ldg(wr + 4 * H + ncol0));
            bb1[0] = f2tf(__ldg(wr + ncol0 + 8));
            bb1[1] = f2tf(__ldg(wr + 4 * H + ncol0 + 8));
#pragma unroll
            for (int mt = 0; mt < 4; ++mt) {
                float4 av = *(const float4*)(U + (mt * 16 + kk) * FR + lane * 4);
                unsigned a[4] = {__float_as_uint(av.x), __float_as_uint(av.y),
                                 __float_as_uint(av.z), __float_as_uint(av.w)};
                mma_tf32(acc[mt][0], a, bb0);
                mma_tf32(acc[mt][1], a, bb1);
            }
        }

        // ---- phase 3: silu + shuffle-paired v4 scatter ----
#pragma unroll
        for (int mt = 0; mt < 4; ++mt) {
            const int e_lo = mt * 16 + g;
            const int e_hi = e_lo + 8;
#pragma unroll
            for (int j = 0; j < 2; ++j) {
                float v0 = silu_f(acc[mt][j][0] + b2v[j][0]);
                float v1 = silu_f(acc[mt][j][1] + b2v[j][1]);
                float v2 = silu_f(acc[mt][j][2] + b2v[j][0]);
                float v3 = silu_f(acc[mt][j][3] + b2v[j][1]);
                float w0 = __shfl_xor_sync(0xffffffffu, v0, 1);
                float w1 = __shfl_xor_sync(0xffffffffu, v1, 1);
                float w2 = __shfl_xor_sync(0xffffffffu, v2, 1);
                float w3 = __shfl_xor_sync(0xffffffffu, v3, 1);
                if ((t & 1) == 0) {
                    const int col4 = wn * 16 + j * 8 + t * 2;
                    if (e_lo < cnt)
                        red_add_v4(agg + (size_t)sdst[e_lo] * H + col4, v0, v1, w0, w1);
                    if (e_hi < cnt)
                        red_add_v4(agg + (size_t)sdst[e_hi] * H + col4, v2, v3, w2, w3);
                }
            }
        }
        __syncthreads();
    }
}

// ---------------- small utility kernels --------------------------------------
__global__ void copy_kernel(float* __restrict__ dst, const float* __restrict__ src, int n) {
    int i = blockIdx.x * blockDim.x + threadIdx.x;
    if (i < n) dst[i] = src[i];
}
__global__ void add_kernel(float* __restrict__ dst, const float* __restrict__ src, int n) {
    int i = blockIdx.x * blockDim.x + threadIdx.x;
    if (i < n) dst[i] += src[i];
}
// zero agg + dpos, init wnode to cb2[0]
__global__ void zero3_kernel(float* __restrict__ a, int n1, float* __restrict__ b, int n2,
                             float* __restrict__ w, int n3, const float* __restrict__ cb2) {
    int i = blockIdx.x * blockDim.x + threadIdx.x;
    if (i < n1) a[i] = 0.0f;
    else if (i - n1 < n2) b[i - n1] = 0.0f;
    else if (i - n1 - n2 < n3) w[i - n1 - n2] = cb2[0];
}

// ---------------- host orchestration -----------------------------------------
extern "C" void kernel_launch(void* const* d_in, const int* in_sizes, int n_in,
                              void* d_out, int out_size)
{
    const float* h_in   = (const float*)d_in[0];
    const float* pos_in = (const float*)d_in[1];
    const int*   ei     = (const int*)d_in[2];
    const float* embW   = (const float*)d_in[3];
    const float* embB   = (const float*)d_in[4];
    const float* msgW1  = (const float*)d_in[5];
    const float* msgB1  = (const float*)d_in[6];
    const float* msgW2  = (const float*)d_in[7];
    const float* msgB2  = (const float*)d_in[8];
    const float* cW1    = (const float*)d_in[9];
    const float* cB1    = (const float*)d_in[10];
    const float* cW2    = (const float*)d_in[11];
    const float* cB2    = (const float*)d_in[12];
    const float* nW1    = (const float*)d_in[13];
    const float* nB1    = (const float*)d_in[14];
    const float* nW2    = (const float*)d_in[15];
    const float* nB2    = (const float*)d_in[16];
    const float* oW1    = (const float*)d_in[17];
    const float* oB1    = (const float*)d_in[18];
    const float* oW2    = (const float*)d_in[19];
    const float* oB2    = (const float*)d_in[20];

    const int N = in_sizes[1] / 3;
    const int E = in_sizes[2] / 2;
    const int Etot = E + N;
    const int INDIM = in_sizes[0] / N;

    float *bh, *bA, *bB, *bagg, *bT, *bpos, *bdpos, *bwn;
    cudaGetSymbolAddress((void**)&bh, g_h);
    cudaGetSymbolAddress((void**)&bA, g_A);
    cudaGetSymbolAddress((void**)&bB, g_B);
    cudaGetSymbolAddress((void**)&bagg, g_agg);
    cudaGetSymbolAddress((void**)&bT, g_T);
    cudaGetSymbolAddress((void**)&bpos, g_pos);
    cudaGetSymbolAddress((void**)&bdpos, g_dpos);
    cudaGetSymbolAddress((void**)&bwn, g_wnode);

    const int NODE_SMEM = 64 * FR * 4;                       // 34816 B
    const int EDGE_SMEM = 64 * FR * 4 + TE * 4 + 2 * TE * 4; // 35584 B
    cudaFuncSetAttribute(node_gemm,
                         cudaFuncAttributeMaxDynamicSharedMemorySize, NODE_SMEM);
    cudaFuncSetAttribute(fused3_gemm,
                         cudaFuncAttributeMaxDynamicSharedMemorySize, NODE_SMEM);
    cudaFuncSetAttribute(edge_kernel,
                         cudaFuncAttributeMaxDynamicSharedMemorySize, EDGE_SMEM);

    const int gn = (N + 63) / 64;
    const int t256p = (N * 3 + 255) / 256;
    const int nz = N * H + N * 3 + N;

    node_gemm<<<gn, 256, NODE_SMEM>>>(h_in, INDIM, nullptr, 0, embW, embB,
                                      nullptr, 0, bh, N);
    copy_kernel<<<t256p, 256>>>(bpos, pos_in, N * 3);

    for (int l = 0; l < LAYERS; ++l) {
        const float* W1a = msgW1 + (size_t)l * 257 * H;
        const float* W1b = W1a + 128 * H;
        const float* W1c = msgW1 + (size_t)l * 257 * H + 256 * H;

        zero3_kernel<<<(nz + 255) / 256, 256>>>(bagg, N * H, bdpos, N * 3,
                                                bwn, N, cB2 + l);
        fused3_gemm<<<dim3(gn, 3), 256, NODE_SMEM>>>(
            bh, cW1 + (size_t)l * H * H, cB1 + l * H, cW2 + (size_t)l * H, bwn,
            W1a, W1b, bA, bB, N);

        edge_kernel<<<444, 256, EDGE_SMEM>>>(
            ei, E, Etot, bA, bB, bpos, bwn,
            msgW2 + (size_t)l * H * H, msgB1 + l * H, msgB2 + l * H, W1c,
            bagg, bdpos);

        node_gemm<<<gn, 256, NODE_SMEM>>>(bh, H, bagg, H, nW1 + (size_t)l * 2 * H * H,
                                          nB1 + l * H, nullptr, 1, bT, N);
        node_gemm<<<gn, 256, NODE_SMEM>>>(bT, H, nullptr, 0, nW2 + (size_t)l * H * H,
                                          nB2 + l * H, bh, 0, bh, N);
        add_kernel<<<t256p, 256>>>(bpos, bdpos, N * 3);
    }

    node_gemm<<<gn, 256, NODE_SMEM>>>(bh, H, nullptr, 0, oW1, oB1, nullptr, 1, bT, N);
    node_gemm<<<gn, 256, NODE_SMEM>>>(bT, H, nullptr, 0, oW2, oB2, nullptr, 0,
                                      (float*)d_out, N);

    if (out_size >= N * H + N * 3) {
        copy_kernel<<<t256p, 256>>>((float*)d_out + (size_t)N * H, bpos, N * 3);
    }
}